// round 7
// baseline (speedup 1.0000x reference)
#include <cuda_runtime.h>
#include <cstddef>

#define D_MODEL 1024
#define NHEADS  16
#define HD      64
#define BATCH   2
#define TSEQ    2048
#define MROWS   (BATCH*TSEQ)   /* 4096 */

// Scratch (device globals). All hold tf32 bit patterns (valid fp32, low 13
// mantissa bits zero) except d_out which gets full fp32.
__device__ float g_xc[(size_t)MROWS * D_MODEL];     // x rounded to tf32
__device__ float g_wq[(size_t)D_MODEL * D_MODEL];
__device__ float g_wk[(size_t)D_MODEL * D_MODEL];
__device__ float g_wv[(size_t)D_MODEL * D_MODEL];
__device__ float g_wo[(size_t)D_MODEL * D_MODEL];
__device__ float g_q[(size_t)MROWS * D_MODEL];      // [B,H,T,64]
__device__ float g_k[(size_t)MROWS * D_MODEL];      // [B,H,T,64]
__device__ float g_v[(size_t)MROWS * D_MODEL];      // TRANSPOSED [B,H,64,T]
__device__ float g_attn[(size_t)MROWS * D_MODEL];   // [B,T,1024]

// ---------------------------------------------------------------------------
// helpers
// ---------------------------------------------------------------------------
__device__ __forceinline__ unsigned f2tf32(float x) {
    unsigned r; asm("cvt.rna.tf32.f32 %0, %1;" : "=r"(r) : "f"(x)); return r;
}
__device__ __forceinline__ float f2tf32f(float x) { return __uint_as_float(f2tf32(x)); }

__device__ __forceinline__ void mma_tf32(float c[4], const unsigned a[4], const unsigned b[2]) {
    asm volatile(
        "mma.sync.aligned.m16n8k8.row.col.f32.tf32.tf32.f32 "
        "{%0,%1,%2,%3}, {%4,%5,%6,%7}, {%8,%9}, {%0,%1,%2,%3};"
        : "+f"(c[0]), "+f"(c[1]), "+f"(c[2]), "+f"(c[3])
        : "r"(a[0]), "r"(a[1]), "r"(a[2]), "r"(a[3]), "r"(b[0]), "r"(b[1]));
}
__device__ __forceinline__ void ldsm4(unsigned &d0, unsigned &d1, unsigned &d2, unsigned &d3,
                                      unsigned addr) {
    asm volatile("ldmatrix.sync.aligned.m8n8.x4.shared.b16 {%0,%1,%2,%3}, [%4];"
                 : "=r"(d0), "=r"(d1), "=r"(d2), "=r"(d3) : "r"(addr));
}
__device__ __forceinline__ void cpa16(unsigned dst, const void* src) {
    asm volatile("cp.async.cg.shared.global [%0], [%1], 16;" :: "r"(dst), "l"(src));
}
__device__ __forceinline__ void cpcommit() { asm volatile("cp.async.commit_group;"); }
template<int N> __device__ __forceinline__ void cpwait() {
    asm volatile("cp.async.wait_group %0;" :: "n"(N) : "memory");
}

// fast exp2 for x <= 0 (FMA pipe, no MUFU)
__device__ __forceinline__ float exp2p(float x) {
    x = fmaxf(x, -126.f);
    float z = x + 12582912.0f;
    int   n = __float_as_int(z) - 0x4B400000;
    float f = x - (z - 12582912.0f);
    float p = 0.0096181291f;
    p = fmaf(p, f, 0.0555041087f);
    p = fmaf(p, f, 0.2402265069f);
    p = fmaf(p, f, 0.6931471806f);
    p = fmaf(p, f, 1.0f);
    return __int_as_float(__float_as_int(p) + (n << 23));
}

// ---------------------------------------------------------------------------
// input pre-conversion: rna-round x and the 4 weight matrices to tf32
// ---------------------------------------------------------------------------
__global__ __launch_bounds__(256) void cvt_in(
    const float4* __restrict__ x,
    const float4* __restrict__ wq, const float4* __restrict__ wk,
    const float4* __restrict__ wv, const float4* __restrict__ wo)
{
    const size_t i = (size_t)blockIdx.x * 256 + threadIdx.x;   // 0 .. 2M-1
    const float4* src; float4* dst;
    if (i < (1u << 20)) {
        src = x + i;  dst = (float4*)g_xc + i;
    } else {
        size_t j = i - (1u << 20);
        int ww = (int)(j >> 18);
        size_t o = j & ((1u << 18) - 1);
        const float4* s = (ww == 0) ? wq : (ww == 1) ? wk : (ww == 2) ? wv : wo;
        float4*       d = (ww == 0) ? (float4*)g_wq : (ww == 1) ? (float4*)g_wk
                                    : (ww == 2) ? (float4*)g_wv : (float4*)g_wo;
        src = s + o; dst = d + o;
    }
    float4 v = *src;
    float4 r;
    r.x = f2tf32f(v.x); r.y = f2tf32f(v.y); r.z = f2tf32f(v.z); r.w = f2tf32f(v.w);
    *dst = r;
}

// ---------------------------------------------------------------------------
// tf32 GEMM: C = A @ W^T, inputs already tf32. 128x128x32 tiles, 8 warps,
// warp tile 64x32. 3-stage cp.async, XOR-swizzled smem, ldmatrix.x4, no cvt.
// EPI: 0 plain fp32; 1 Q/K permute ([B,H,T,64], tf32); 2 V transpose
// ([B,H,64,T], tf32).
// ---------------------------------------------------------------------------
#define GT 4096                         /* floats per 128x32 tile */

template <int EPI>
__device__ __forceinline__ void gemm_body(const float* __restrict__ A,
                                          const float* __restrict__ W,
                                          float* __restrict__ C)
{
    extern __shared__ float gsm[];
    const unsigned sA = (unsigned)__cvta_generic_to_shared(gsm);
    const unsigned sB = sA + 3 * GT * 4;

    const int tid  = threadIdx.x;
    const int lane = tid & 31;
    const int warp = tid >> 5;
    const int wm   = warp >> 2;
    const int wn   = warp & 3;
    const int bx   = blockIdx.x;
    const int by   = blockIdx.y;

    const int lr16 = lane & 15;
    const int lhi  = lane >> 4;
    const int lx7  = lane & 7;
    const int r4   = lane >> 2;
    const int c4   = lane & 3;

    const int fu = tid & 7;
    const int fr = tid >> 3;
    const float* Ag = A + (size_t)(by * 128) * 1024 + fu * 4;
    const float* Wg = W + (size_t)(bx * 128) * 1024 + fu * 4;

    const unsigned a_row = (unsigned)(wm * 64 + lr16) * 128;
    const unsigned b_row = (unsigned)(wn * 32 + lr16) * 128;
    unsigned colb[4];
#pragma unroll
    for (int ks = 0; ks < 4; ks++) colb[ks] = (unsigned)(((ks * 2 + lhi) ^ lx7) * 16);

    float acc[4][4][4];
#pragma unroll
    for (int mt = 0; mt < 4; mt++)
#pragma unroll
        for (int nt = 0; nt < 4; nt++)
#pragma unroll
            for (int e = 0; e < 4; e++) acc[mt][nt][e] = 0.f;

#pragma unroll
    for (int pk = 0; pk < 2; pk++) {
        const unsigned ab = sA + pk * GT * 4;
        const unsigned bb = sB + pk * GT * 4;
#pragma unroll
        for (int i = 0; i < 4; i++) {
            const int r = fr + i * 32;
            const unsigned off = (unsigned)((r * 8 + (fu ^ (r & 7))) * 16);
            cpa16(ab + off, Ag + (size_t)r * 1024 + pk * 32);
            cpa16(bb + off, Wg + (size_t)r * 1024 + pk * 32);
        }
        cpcommit();
    }

    for (int ki = 0; ki < 32; ki++) {
        cpwait<1>();
        __syncthreads();

        if (ki + 2 < 32) {
            const int st = (ki + 2) % 3;
            const unsigned ab = sA + st * GT * 4;
            const unsigned bb = sB + st * GT * 4;
#pragma unroll
            for (int i = 0; i < 4; i++) {
                const int r = fr + i * 32;
                const unsigned off = (unsigned)((r * 8 + (fu ^ (r & 7))) * 16);
                cpa16(ab + off, Ag + (size_t)r * 1024 + (ki + 2) * 32);
                cpa16(bb + off, Wg + (size_t)r * 1024 + (ki + 2) * 32);
            }
        }
        cpcommit();

        const int s = ki % 3;
        const unsigned ab = sA + s * GT * 4;
        const unsigned bb = sB + s * GT * 4;
#pragma unroll
        for (int ks = 0; ks < 4; ks++) {
            unsigned af[4][4];
#pragma unroll
            for (int mt = 0; mt < 4; mt++)
                ldsm4(af[mt][0], af[mt][1], af[mt][2], af[mt][3],
                      ab + a_row + mt * 2048 + colb[ks]);
            unsigned bf[2][4];
#pragma unroll
            for (int n2 = 0; n2 < 2; n2++)
                ldsm4(bf[n2][0], bf[n2][1], bf[n2][2], bf[n2][3],
                      bb + b_row + n2 * 2048 + colb[ks]);
#pragma unroll
            for (int mt = 0; mt < 4; mt++)
#pragma unroll
                for (int nt = 0; nt < 4; nt++) {
                    const int n2 = nt >> 1, sub = nt & 1;
                    unsigned bq[2] = { bf[n2][sub], bf[n2][sub + 2] };
                    mma_tf32(acc[mt][nt], af[mt], bq);
                }
        }
    }

#pragma unroll
    for (int mt = 0; mt < 4; mt++) {
        const int row0 = by * 128 + wm * 64 + mt * 16 + r4;
#pragma unroll
        for (int nt = 0; nt < 4; nt++) {
            const int col = bx * 128 + wn * 32 + nt * 8 + 2 * c4;
            if (EPI == 0) {
                *(float2*)&C[(size_t)row0 * 1024 + col] =
                    make_float2(acc[mt][nt][0], acc[mt][nt][1]);
                *(float2*)&C[(size_t)(row0 + 8) * 1024 + col] =
                    make_float2(acc[mt][nt][2], acc[mt][nt][3]);
            } else if (EPI == 1) {
                const int h = col >> 6, d = col & 63;
                const int b2 = row0 >> 11, t0 = row0 & 2047;
                float* base = C + (((size_t)(b2 * NHEADS + h)) * TSEQ) * HD + d;
                *(float2*)(base + (size_t)t0 * HD) =
                    make_float2(f2tf32f(acc[mt][nt][0]), f2tf32f(acc[mt][nt][1]));
                *(float2*)(base + (size_t)(t0 + 8) * HD) =
                    make_float2(f2tf32f(acc[mt][nt][2]), f2tf32f(acc[mt][nt][3]));
            } else {
                const int h = col >> 6, d = col & 63;
                const int b2 = row0 >> 11, t0 = row0 & 2047;
                float* base = C + ((size_t)(b2 * NHEADS + h) * HD + d) * TSEQ;
                base[t0]            = f2tf32f(acc[mt][nt][0]);
                base[TSEQ + t0]     = f2tf32f(acc[mt][nt][1]);
                base[t0 + 8]        = f2tf32f(acc[mt][nt][2]);
                base[TSEQ + t0 + 8] = f2tf32f(acc[mt][nt][3]);
            }
        }
    }
}

__global__ __launch_bounds__(256) void gemm_qkv_tc() {
    if (blockIdx.z == 0)      gemm_body<1>(g_xc, g_wq, g_q);
    else if (blockIdx.z == 1) gemm_body<1>(g_xc, g_wk, g_k);
    else                      gemm_body<2>(g_xc, g_wv, g_v);
}
__global__ __launch_bounds__(256) void gemm_o_tc(float* __restrict__ out) {
    gemm_body<0>(g_attn, g_wo, out);
}

// ---------------------------------------------------------------------------
// Flash attention, tf32, causal. 256 threads (8 warps), 128 q rows per block;
// warp w owns rows w*16..+15. K tiles [64k][64d], Vt tiles [64d][64k],
// 3-stage cp.async, ldmatrix fragments, per-warp P smem. Fully-masked key
// tiles are skipped per warp.
// ---------------------------------------------------------------------------
#define AT 4096                                        /* floats per 64x64 tile */
#define ATTN_SMEM_BYTES ((6*AT + 8*16*64) * 4)         /* 131072 */

__global__ __launch_bounds__(256) void attn_tc() {
    extern __shared__ float asm_[];
    float* Pbuf = asm_ + 6 * AT;
    const unsigned sK = (unsigned)__cvta_generic_to_shared(asm_);
    const unsigned sV = sK + 3 * AT * 4;

    const int tid  = threadIdx.x;
    const int lane = tid & 31;
    const int w    = tid >> 5;            // 0..7
    const int r4   = lane >> 2;
    const int c4   = lane & 3;
    const int lr16 = lane & 15;
    const int lhi  = lane >> 4;
    const int lx7  = lane & 7;
    const int bh   = blockIdx.y;
    const int qt   = (int)gridDim.x - 1 - (int)blockIdx.x;   // heavy first

    const float* Kg = g_k + (size_t)bh * TSEQ * HD;   // [t][d]
    const float* Vg = g_v + (size_t)bh * HD * TSEQ;   // [d][t]

    float* Pw = Pbuf + w * 16 * 64;
    const unsigned sP = (unsigned)__cvta_generic_to_shared(Pw);

    // fill mapping: 64 rows x 16 float4-units per tile, 256 threads -> 4 iters
    const int fu = tid & 15;
    const int fr = tid >> 4;              // 0..15

    const int qbase = qt * 128 + w * 16;  // first q row of this warp

    unsigned qf[8][4];
    {
        const float* Qb = g_q + ((size_t)bh * TSEQ + qbase) * HD;
#pragma unroll
        for (int ks = 0; ks < 8; ks++) {
            qf[ks][0] = __float_as_uint(Qb[(r4    ) * HD + ks*8 + c4    ]);
            qf[ks][1] = __float_as_uint(Qb[(r4 + 8) * HD + ks*8 + c4    ]);
            qf[ks][2] = __float_as_uint(Qb[(r4    ) * HD + ks*8 + c4 + 4]);
            qf[ks][3] = __float_as_uint(Qb[(r4 + 8) * HD + ks*8 + c4 + 4]);
        }
    }

    unsigned colb[8];
#pragma unroll
    for (int ks = 0; ks < 8; ks++) colb[ks] = (unsigned)(((ks * 2 + lhi) ^ lx7) * 16);
    const unsigned rowb = (unsigned)lr16 * 256;

    float oacc[8][4];
#pragma unroll
    for (int dt = 0; dt < 8; dt++)
#pragma unroll
        for (int e = 0; e < 4; e++) oacc[dt][e] = 0.f;
    float rm0 = -1e30f, rm1 = -1e30f, rl0 = 0.f, rl1 = 0.f;

    const int qrow0 = qbase + r4;
    const int qrow1 = qrow0 + 8;
    const float SC2 = 0.1803368801f;      // (1/8)*log2(e)

    const int ktiles = 2 * (qt + 1);

#pragma unroll
    for (int pk = 0; pk < 2; pk++) {
        const unsigned ka = sK + pk * AT * 4;
        const unsigned va = sV + pk * AT * 4;
#pragma unroll
        for (int i = 0; i < 4; i++) {
            const int r = fr + i * 16;
            const unsigned off = (unsigned)((r * 16 + (fu ^ (r & 7))) * 16);
            cpa16(ka + off, Kg + (size_t)(pk * 64 + r) * HD + fu * 4);
            cpa16(va + off, Vg + (size_t)r * TSEQ + pk * 64 + fu * 4);
        }
        cpcommit();
    }

    for (int kt = 0; kt < ktiles; kt++) {
        cpwait<1>();
        __syncthreads();

        if (kt + 2 < ktiles) {
            const int st = (kt + 2) % 3;
            const unsigned ka = sK + st * AT * 4;
            const unsigned va = sV + st * AT * 4;
#pragma unroll
            for (int i = 0; i < 4; i++) {
                const int r = fr + i * 16;
                const unsigned off = (unsigned)((r * 16 + (fu ^ (r & 7))) * 16);
                cpa16(ka + off, Kg + (size_t)((kt + 2) * 64 + r) * HD + fu * 4);
                cpa16(va + off, Vg + (size_t)r * TSEQ + (kt + 2) * 64 + fu * 4);
            }
        }
        cpcommit();

        const int ktbase = kt * 64;
        // fully masked for this warp? (all keys strictly future of all rows)
        if (ktbase > qbase + 15) continue;

        const int s = kt % 3;
        const unsigned ka = sK + s * AT * 4;
        const unsigned va = sV + s * AT * 4;

        // S = Q @ K^T (16 x 64 per warp)
        float sf[8][4];
#pragma unroll
        for (int nt = 0; nt < 8; nt++)
#pragma unroll
            for (int e = 0; e < 4; e++) sf[nt][e] = 0.f;
#pragma unroll
        for (int ks = 0; ks < 8; ks++) {
#pragma unroll
            for (int g = 0; g < 4; g++) {
                unsigned d0, d1, d2, d3;
                ldsm4(d0, d1, d2, d3, ka + g * 4096 + rowb + colb[ks]);
                unsigned b0[2] = { d0, d2 };
                unsigned b1[2] = { d1, d3 };
                mma_tf32(sf[2*g    ], qf[ks], b0);
                mma_tf32(sf[2*g + 1], qf[ks], b1);
            }
        }

        const bool needm = (ktbase + 63 > qbase);
#pragma unroll
        for (int nt = 0; nt < 8; nt++) {
            sf[nt][0] *= SC2; sf[nt][1] *= SC2; sf[nt][2] *= SC2; sf[nt][3] *= SC2;
            if (needm) {
                const int kc = ktbase + nt * 8 + 2 * c4;
                if (kc     > qrow0) sf[nt][0] = -1e30f;
                if (kc + 1 > qrow0) sf[nt][1] = -1e30f;
                if (kc     > qrow1) sf[nt][2] = -1e30f;
                if (kc + 1 > qrow1) sf[nt][3] = -1e30f;
            }
        }

        float mx0 = -1e30f, mx1 = -1e30f;
#pragma unroll
        for (int nt = 0; nt < 8; nt++) {
            mx0 = fmaxf(mx0, fmaxf(sf[nt][0], sf[nt][1]));
            mx1 = fmaxf(mx1, fmaxf(sf[nt][2], sf[nt][3]));
        }
        mx0 = fmaxf(mx0, __shfl_xor_sync(0xffffffffu, mx0, 1));
        mx0 = fmaxf(mx0, __shfl_xor_sync(0xffffffffu, mx0, 2));
        mx1 = fmaxf(mx1, __shfl_xor_sync(0xffffffffu, mx1, 1));
        mx1 = fmaxf(mx1, __shfl_xor_sync(0xffffffffu, mx1, 2));

        const float nm0 = fmaxf(rm0, mx0), nm1 = fmaxf(rm1, mx1);
        const float corr0 = exp2p(rm0 - nm0), corr1 = exp2p(rm1 - nm1);
        rm0 = nm0; rm1 = nm1;

        float s0 = 0.f, s1 = 0.f;
#pragma unroll
        for (int nt = 0; nt < 8; nt++) {
            const float p0 = exp2p(sf[nt][0] - nm0);
            const float p1 = exp2p(sf[nt][1] - nm0);
            const float p2 = exp2p(sf[nt][2] - nm1);
            const float p3 = exp2p(sf[nt][3] - nm1);
            s0 += p0 + p1;  s1 += p2 + p3;
            const int col = nt * 8 + 2 * c4;
            const int u   = col >> 2;
            const int wd  = col & 3;
            Pw[(r4    ) * 64 + ((u ^ r4) << 2) + wd    ] = f2tf32f(p0);
            Pw[(r4    ) * 64 + ((u ^ r4) << 2) + wd + 1] = f2tf32f(p1);
            Pw[(r4 + 8) * 64 + ((u ^ r4) << 2) + wd    ] = f2tf32f(p2);
            Pw[(r4 + 8) * 64 + ((u ^ r4) << 2) + wd + 1] = f2tf32f(p3);
        }
        s0 += __shfl_xor_sync(0xffffffffu, s0, 1);
        s0 += __shfl_xor_sync(0xffffffffu, s0, 2);
        s1 += __shfl_xor_sync(0xffffffffu, s1, 1);
        s1 += __shfl_xor_sync(0xffffffffu, s1, 2);
        rl0 = rl0 * corr0 + s0;
        rl1 = rl1 * corr1 + s1;

#pragma unroll
        for (int dt = 0; dt < 8; dt++) {
            oacc[dt][0] *= corr0; oacc[dt][1] *= corr0;
            oacc[dt][2] *= corr1; oacc[dt][3] *= corr1;
        }
        __syncwarp();

#pragma unroll
        for (int ks = 0; ks < 8; ks++) {
            unsigned pf[4];
            ldsm4(pf[0], pf[1], pf[2], pf[3], sP + rowb + colb[ks]);
#pragma unroll
            for (int g = 0; g < 4; g++) {
                unsigned d0, d1, d2, d3;
                ldsm4(d0, d1, d2, d3, va + g * 4096 + rowb + colb[ks]);
                unsigned b0[2] = { d0, d2 };
                unsigned b1[2] = { d1, d3 };
                mma_tf32(oacc[2*g    ], pf, b0);
                mma_tf32(oacc[2*g + 1], pf, b1);
            }
        }
        __syncwarp();
    }

    const float inv0 = 1.f / rl0;
    const float inv1 = 1.f / rl1;
    const int bb = bh >> 4;
    const int h  = bh & 15;
    const size_t rg = (size_t)(bb * TSEQ + qt * 128 + w * 16 + r4);
    float* O0 = g_attn + rg * D_MODEL + h * HD;
    float* O1 = O0 + 8 * D_MODEL;
#pragma unroll
    for (int dt = 0; dt < 8; dt++) {
        const int dim = dt * 8 + 2 * c4;
        *(float2*)(O0 + dim) = make_float2(f2tf32f(oacc[dt][0] * inv0),
                                           f2tf32f(oacc[dt][1] * inv0));
        *(float2*)(O1 + dim) = make_float2(f2tf32f(oacc[dt][2] * inv1),
                                           f2tf32f(oacc[dt][3] * inv1));
    }
}

// ---------------------------------------------------------------------------
extern "C" void kernel_launch(void* const* d_in, const int* in_sizes, int n_in,
                              void* d_out, int out_size)
{
    const float* x  = (const float*)d_in[0];
    const float* Wq = (const float*)d_in[1];
    const float* Wk = (const float*)d_in[2];
    const float* Wv = (const float*)d_in[3];
    const float* Wo = (const float*)d_in[4];
    float* out = (float*)d_out;

    const int gemm_smem = 6 * GT * (int)sizeof(float);   // 98304
    const int attn_smem = ATTN_SMEM_BYTES;               // 131072
    cudaFuncSetAttribute(gemm_qkv_tc, cudaFuncAttributeMaxDynamicSharedMemorySize, gemm_smem);
    cudaFuncSetAttribute(gemm_o_tc,   cudaFuncAttributeMaxDynamicSharedMemorySize, gemm_smem);
    cudaFuncSetAttribute(attn_tc,     cudaFuncAttributeMaxDynamicSharedMemorySize, attn_smem);

    cvt_in<<<8192, 256>>>((const float4*)x, (const float4*)Wq, (const float4*)Wk,
                          (const float4*)Wv, (const float4*)Wo);

    dim3 gqkv(1024 / 128, MROWS / 128, 3);
    gemm_qkv_tc<<<gqkv, 256, gemm_smem>>>();

    dim3 gattn(TSEQ / 128, BATCH * NHEADS);
    attn_tc<<<gattn, 256, attn_smem>>>();

    dim3 go(1024 / 128, MROWS / 128);
    gemm_o_tc<<<go, 256, gemm_smem>>>(out);
}

// round 11
// speedup vs baseline: 1.1345x; 1.1345x over previous
#include <cuda_runtime.h>
#include <cstddef>

#define D_MODEL 1024
#define NHEADS  16
#define HD      64
#define BATCH   2
#define TSEQ    2048
#define MROWS   (BATCH*TSEQ)   /* 4096 */

// Scratch (device globals). All hold tf32 bit patterns (valid fp32, low 13
// mantissa bits zero) except d_out which gets full fp32.
__device__ float g_xc[(size_t)MROWS * D_MODEL];     // x rounded to tf32
__device__ float g_wq[(size_t)D_MODEL * D_MODEL];
__device__ float g_wk[(size_t)D_MODEL * D_MODEL];
__device__ float g_wv[(size_t)D_MODEL * D_MODEL];
__device__ float g_wo[(size_t)D_MODEL * D_MODEL];
__device__ float g_q[(size_t)MROWS * D_MODEL];      // [B,H,T,64]
__device__ float g_k[(size_t)MROWS * D_MODEL];      // [B,H,T,64]
__device__ float g_v[(size_t)MROWS * D_MODEL];      // TRANSPOSED [B,H,64,T]
__device__ float g_attn[(size_t)MROWS * D_MODEL];   // [B,T,1024]

// ---------------------------------------------------------------------------
// helpers
// ---------------------------------------------------------------------------
__device__ __forceinline__ unsigned f2tf32(float x) {
    unsigned r; asm("cvt.rna.tf32.f32 %0, %1;" : "=r"(r) : "f"(x)); return r;
}
__device__ __forceinline__ float f2tf32f(float x) { return __uint_as_float(f2tf32(x)); }

__device__ __forceinline__ void mma_tf32(float c[4], const unsigned a[4], const unsigned b[2]) {
    asm volatile(
        "mma.sync.aligned.m16n8k8.row.col.f32.tf32.tf32.f32 "
        "{%0,%1,%2,%3}, {%4,%5,%6,%7}, {%8,%9}, {%0,%1,%2,%3};"
        : "+f"(c[0]), "+f"(c[1]), "+f"(c[2]), "+f"(c[3])
        : "r"(a[0]), "r"(a[1]), "r"(a[2]), "r"(a[3]), "r"(b[0]), "r"(b[1]));
}
__device__ __forceinline__ void ldsm4(unsigned &d0, unsigned &d1, unsigned &d2, unsigned &d3,
                                      unsigned addr) {
    asm volatile("ldmatrix.sync.aligned.m8n8.x4.shared.b16 {%0,%1,%2,%3}, [%4];"
                 : "=r"(d0), "=r"(d1), "=r"(d2), "=r"(d3) : "r"(addr));
}
__device__ __forceinline__ void cpa16(unsigned dst, const void* src) {
    asm volatile("cp.async.cg.shared.global [%0], [%1], 16;" :: "r"(dst), "l"(src));
}
__device__ __forceinline__ void cpcommit() { asm volatile("cp.async.commit_group;"); }
template<int N> __device__ __forceinline__ void cpwait() {
    asm volatile("cp.async.wait_group %0;" :: "n"(N) : "memory");
}

// fast exp2 for x <= 0 (FMA pipe, no MUFU)
__device__ __forceinline__ float exp2p(float x) {
    x = fmaxf(x, -126.f);
    float z = x + 12582912.0f;
    int   n = __float_as_int(z) - 0x4B400000;
    float f = x - (z - 12582912.0f);
    float p = 0.0096181291f;
    p = fmaf(p, f, 0.0555041087f);
    p = fmaf(p, f, 0.2402265069f);
    p = fmaf(p, f, 0.6931471806f);
    p = fmaf(p, f, 1.0f);
    return __int_as_float(__float_as_int(p) + (n << 23));
}

// ---------------------------------------------------------------------------
// input pre-conversion: rna-round x and the 4 weight matrices to tf32
// ---------------------------------------------------------------------------
__global__ __launch_bounds__(256) void cvt_in(
    const float4* __restrict__ x,
    const float4* __restrict__ wq, const float4* __restrict__ wk,
    const float4* __restrict__ wv, const float4* __restrict__ wo)
{
    const size_t i = (size_t)blockIdx.x * 256 + threadIdx.x;   // 0 .. 2M-1
    const float4* src; float4* dst;
    if (i < (1u << 20)) {
        src = x + i;  dst = (float4*)g_xc + i;
    } else {
        size_t j = i - (1u << 20);
        int ww = (int)(j >> 18);
        size_t o = j & ((1u << 18) - 1);
        const float4* s = (ww == 0) ? wq : (ww == 1) ? wk : (ww == 2) ? wv : wo;
        float4*       d = (ww == 0) ? (float4*)g_wq : (ww == 1) ? (float4*)g_wk
                                    : (ww == 2) ? (float4*)g_wv : (float4*)g_wo;
        src = s + o; dst = d + o;
    }
    float4 v = *src;
    float4 r;
    r.x = f2tf32f(v.x); r.y = f2tf32f(v.y); r.z = f2tf32f(v.z); r.w = f2tf32f(v.w);
    *dst = r;
}

// ---------------------------------------------------------------------------
// tf32 GEMM: C = A @ W^T, inputs already tf32. Block tile 128x256, k-chunk 32,
// 8 warps with 64x64 warp tiles (2 x 4). 3-stage cp.async, XOR-swizzled smem,
// ldmatrix.x4 fragments, no cvt in mainloop.
// EPI: 0 plain fp32; 1 Q/K permute ([B,H,T,64], tf32); 2 V transpose
// ([B,H,64,T], tf32).
// ---------------------------------------------------------------------------
#define GSA (128*32)                    /* A floats per stage */
#define GSB (256*32)                    /* B floats per stage */
#define GEMM_SMEM_BYTES ((GSA+GSB)*3*4) /* 147456 */

template <int EPI>
__device__ __forceinline__ void gemm_body(const float* __restrict__ A,
                                          const float* __restrict__ W,
                                          float* __restrict__ C)
{
    extern __shared__ float gsm[];
    const unsigned sA = (unsigned)__cvta_generic_to_shared(gsm);
    const unsigned sB = sA + 3 * GSA * 4;

    const int tid  = threadIdx.x;
    const int lane = tid & 31;
    const int warp = tid >> 5;
    const int wm   = warp >> 2;          // 0..1  (64 rows)
    const int wn   = warp & 3;           // 0..3  (64 cols)
    const int bx   = blockIdx.x;
    const int by   = blockIdx.y;

    const int lr16 = lane & 15;
    const int lhi  = lane >> 4;
    const int lx7  = lane & 7;
    const int r4   = lane >> 2;
    const int c4   = lane & 3;

    const int fu = tid & 7;              // float4 unit within 32-float row
    const int fr = tid >> 3;             // 0..31
    const float* Ag = A + (size_t)(by * 128) * 1024 + fu * 4;
    const float* Wg = W + (size_t)(bx * 256) * 1024 + fu * 4;

    const unsigned a_row = (unsigned)(wm * 64 + lr16) * 128;
    const unsigned b_row = (unsigned)(wn * 64 + lr16) * 128;
    unsigned colb[4];
#pragma unroll
    for (int ks = 0; ks < 4; ks++) colb[ks] = (unsigned)(((ks * 2 + lhi) ^ lx7) * 16);

    float acc[4][8][4];
#pragma unroll
    for (int mt = 0; mt < 4; mt++)
#pragma unroll
        for (int nt = 0; nt < 8; nt++)
#pragma unroll
            for (int e = 0; e < 4; e++) acc[mt][nt][e] = 0.f;

#pragma unroll
    for (int pk = 0; pk < 2; pk++) {
        const unsigned ab = sA + pk * GSA * 4;
        const unsigned bb = sB + pk * GSB * 4;
#pragma unroll
        for (int i = 0; i < 4; i++) {
            const int r = fr + i * 32;
            const unsigned off = (unsigned)((r * 8 + (fu ^ (r & 7))) * 16);
            cpa16(ab + off, Ag + (size_t)r * 1024 + pk * 32);
        }
#pragma unroll
        for (int i = 0; i < 8; i++) {
            const int r = fr + i * 32;
            const unsigned off = (unsigned)((r * 8 + (fu ^ (r & 7))) * 16);
            cpa16(bb + off, Wg + (size_t)r * 1024 + pk * 32);
        }
        cpcommit();
    }

    for (int ki = 0; ki < 32; ki++) {
        cpwait<1>();
        __syncthreads();

        if (ki + 2 < 32) {
            const int st = (ki + 2) % 3;
            const unsigned ab = sA + st * GSA * 4;
            const unsigned bb = sB + st * GSB * 4;
#pragma unroll
            for (int i = 0; i < 4; i++) {
                const int r = fr + i * 32;
                const unsigned off = (unsigned)((r * 8 + (fu ^ (r & 7))) * 16);
                cpa16(ab + off, Ag + (size_t)r * 1024 + (ki + 2) * 32);
            }
#pragma unroll
            for (int i = 0; i < 8; i++) {
                const int r = fr + i * 32;
                const unsigned off = (unsigned)((r * 8 + (fu ^ (r & 7))) * 16);
                cpa16(bb + off, Wg + (size_t)r * 1024 + (ki + 2) * 32);
            }
        }
        cpcommit();

        const int s = ki % 3;
        const unsigned ab = sA + s * GSA * 4;
        const unsigned bb = sB + s * GSB * 4;
#pragma unroll
        for (int ks = 0; ks < 4; ks++) {
            unsigned af[4][4];
#pragma unroll
            for (int mt = 0; mt < 4; mt++)
                ldsm4(af[mt][0], af[mt][1], af[mt][2], af[mt][3],
                      ab + a_row + mt * 2048 + colb[ks]);
            unsigned bf[4][4];
#pragma unroll
            for (int n2 = 0; n2 < 4; n2++)
                ldsm4(bf[n2][0], bf[n2][1], bf[n2][2], bf[n2][3],
                      bb + b_row + n2 * 2048 + colb[ks]);
#pragma unroll
            for (int mt = 0; mt < 4; mt++)
#pragma unroll
                for (int nt = 0; nt < 8; nt++) {
                    const int n2 = nt >> 1, sub = nt & 1;
                    unsigned bq[2] = { bf[n2][sub], bf[n2][sub + 2] };
                    mma_tf32(acc[mt][nt], af[mt], bq);
                }
        }
    }

#pragma unroll
    for (int mt = 0; mt < 4; mt++) {
        const int row0 = by * 128 + wm * 64 + mt * 16 + r4;
#pragma unroll
        for (int nt = 0; nt < 8; nt++) {
            const int col = bx * 256 + wn * 64 + nt * 8 + 2 * c4;
            if (EPI == 0) {
                *(float2*)&C[(size_t)row0 * 1024 + col] =
                    make_float2(acc[mt][nt][0], acc[mt][nt][1]);
                *(float2*)&C[(size_t)(row0 + 8) * 1024 + col] =
                    make_float2(acc[mt][nt][2], acc[mt][nt][3]);
            } else if (EPI == 1) {
                const int h = col >> 6, d = col & 63;
                const int b2 = row0 >> 11, t0 = row0 & 2047;
                float* base = C + (((size_t)(b2 * NHEADS + h)) * TSEQ) * HD + d;
                *(float2*)(base + (size_t)t0 * HD) =
                    make_float2(f2tf32f(acc[mt][nt][0]), f2tf32f(acc[mt][nt][1]));
                *(float2*)(base + (size_t)(t0 + 8) * HD) =
                    make_float2(f2tf32f(acc[mt][nt][2]), f2tf32f(acc[mt][nt][3]));
            } else {
                const int h = col >> 6, d = col & 63;
                const int b2 = row0 >> 11, t0 = row0 & 2047;
                float* base = C + ((size_t)(b2 * NHEADS + h) * HD + d) * TSEQ;
                base[t0]            = f2tf32f(acc[mt][nt][0]);
                base[TSEQ + t0]     = f2tf32f(acc[mt][nt][1]);
                base[t0 + 8]        = f2tf32f(acc[mt][nt][2]);
                base[TSEQ + t0 + 8] = f2tf32f(acc[mt][nt][3]);
            }
        }
    }
}

__global__ __launch_bounds__(256, 1) void gemm_qkv_tc() {
    if (blockIdx.z == 0)      gemm_body<1>(g_xc, g_wq, g_q);
    else if (blockIdx.z == 1) gemm_body<1>(g_xc, g_wk, g_k);
    else                      gemm_body<2>(g_xc, g_wv, g_v);
}
__global__ __launch_bounds__(256, 1) void gemm_o_tc(float* __restrict__ out) {
    gemm_body<0>(g_attn, g_wo, out);
}

// ---------------------------------------------------------------------------
// Flash attention, tf32, causal (R6 configuration: 128 threads / 64 q rows).
// ---------------------------------------------------------------------------
#define AT 4096                                      /* floats per 64x64 tile */
#define ATTN_SMEM_BYTES ((6*AT + 4*16*64) * 4)       /* 114688 */

__global__ __launch_bounds__(128) void attn_tc() {
    extern __shared__ float asm_[];
    float* Pbuf = asm_ + 6 * AT;
    const unsigned sK = (unsigned)__cvta_generic_to_shared(asm_);
    const unsigned sV = sK + 3 * AT * 4;

    const int tid  = threadIdx.x;
    const int lane = tid & 31;
    const int w    = tid >> 5;
    const int r4   = lane >> 2;
    const int c4   = lane & 3;
    const int lr16 = lane & 15;
    const int lhi  = lane >> 4;
    const int lx7  = lane & 7;
    const int bh   = blockIdx.y;
    const int qt   = (int)gridDim.x - 1 - (int)blockIdx.x;

    const float* Kg = g_k + (size_t)bh * TSEQ * HD;   // [t][d]
    const float* Vg = g_v + (size_t)bh * HD * TSEQ;   // [d][t]

    float* Pw = Pbuf + w * 16 * 64;
    const unsigned sP = (unsigned)__cvta_generic_to_shared(Pw);

    const int fu = tid & 15;
    const int fr = tid >> 4;

    unsigned qf[8][4];
    {
        const float* Qb = g_q + ((size_t)bh * TSEQ + qt * 64 + w * 16) * HD;
#pragma unroll
        for (int ks = 0; ks < 8; ks++) {
            qf[ks][0] = __float_as_uint(Qb[(r4    ) * HD + ks*8 + c4    ]);
            qf[ks][1] = __float_as_uint(Qb[(r4 + 8) * HD + ks*8 + c4    ]);
            qf[ks][2] = __float_as_uint(Qb[(r4    ) * HD + ks*8 + c4 + 4]);
            qf[ks][3] = __float_as_uint(Qb[(r4 + 8) * HD + ks*8 + c4 + 4]);
        }
    }

    unsigned colb[8];
#pragma unroll
    for (int ks = 0; ks < 8; ks++) colb[ks] = (unsigned)(((ks * 2 + lhi) ^ lx7) * 16);
    const unsigned rowb = (unsigned)lr16 * 256;

    float oacc[8][4];
#pragma unroll
    for (int dt = 0; dt < 8; dt++)
#pragma unroll
        for (int e = 0; e < 4; e++) oacc[dt][e] = 0.f;
    float rm0 = -1e30f, rm1 = -1e30f, rl0 = 0.f, rl1 = 0.f;

    const int rowL0 = w * 16 + r4;
    const int rowL1 = rowL0 + 8;
    const float SC2 = 0.1803368801f;

#pragma unroll
    for (int pk = 0; pk < 2; pk++) {
        if (pk <= qt) {
            const unsigned ka = sK + pk * AT * 4;
            const unsigned va = sV + pk * AT * 4;
#pragma unroll
            for (int i = 0; i < 8; i++) {
                const int r = fr + i * 8;
                const unsigned off = (unsigned)((r * 16 + (fu ^ (r & 7))) * 16);
                cpa16(ka + off, Kg + (size_t)(pk * 64 + r) * HD + fu * 4);
                cpa16(va + off, Vg + (size_t)r * TSEQ + pk * 64 + fu * 4);
            }
        }
        cpcommit();
    }

    for (int kt = 0; kt <= qt; kt++) {
        cpwait<1>();
        __syncthreads();

        if (kt + 2 <= qt) {
            const int st = (kt + 2) % 3;
            const unsigned ka = sK + st * AT * 4;
            const unsigned va = sV + st * AT * 4;
#pragma unroll
            for (int i = 0; i < 8; i++) {
                const int r = fr + i * 8;
                const unsigned off = (unsigned)((r * 16 + (fu ^ (r & 7))) * 16);
                cpa16(ka + off, Kg + (size_t)((kt + 2) * 64 + r) * HD + fu * 4);
                cpa16(va + off, Vg + (size_t)r * TSEQ + (kt + 2) * 64 + fu * 4);
            }
        }
        cpcommit();

        const int s = kt % 3;
        const unsigned ka = sK + s * AT * 4;
        const unsigned va = sV + s * AT * 4;

        float sf[8][4];
#pragma unroll
        for (int nt = 0; nt < 8; nt++)
#pragma unroll
            for (int e = 0; e < 4; e++) sf[nt][e] = 0.f;
#pragma unroll
        for (int ks = 0; ks < 8; ks++) {
#pragma unroll
            for (int g = 0; g < 4; g++) {
                unsigned d0, d1, d2, d3;
                ldsm4(d0, d1, d2, d3, ka + g * 4096 + rowb + colb[ks]);
                unsigned b0[2] = { d0, d2 };
                unsigned b1[2] = { d1, d3 };
                mma_tf32(sf[2*g    ], qf[ks], b0);
                mma_tf32(sf[2*g + 1], qf[ks], b1);
            }
        }

        const bool diag = (kt == qt);
#pragma unroll
        for (int nt = 0; nt < 8; nt++) {
            sf[nt][0] *= SC2; sf[nt][1] *= SC2; sf[nt][2] *= SC2; sf[nt][3] *= SC2;
            if (diag) {
                const int kc = nt * 8 + 2 * c4;
                if (kc     > rowL0) sf[nt][0] = -1e30f;
                if (kc + 1 > rowL0) sf[nt][1] = -1e30f;
                if (kc     > rowL1) sf[nt][2] = -1e30f;
                if (kc + 1 > rowL1) sf[nt][3] = -1e30f;
            }
        }

        float mx0 = -1e30f, mx1 = -1e30f;
#pragma unroll
        for (int nt = 0; nt < 8; nt++) {
            mx0 = fmaxf(mx0, fmaxf(sf[nt][0], sf[nt][1]));
            mx1 = fmaxf(mx1, fmaxf(sf[nt][2], sf[nt][3]));
        }
        mx0 = fmaxf(mx0, __shfl_xor_sync(0xffffffffu, mx0, 1));
        mx0 = fmaxf(mx0, __shfl_xor_sync(0xffffffffu, mx0, 2));
        mx1 = fmaxf(mx1, __shfl_xor_sync(0xffffffffu, mx1, 1));
        mx1 = fmaxf(mx1, __shfl_xor_sync(0xffffffffu, mx1, 2));

        const float nm0 = fmaxf(rm0, mx0), nm1 = fmaxf(rm1, mx1);
        const float corr0 = exp2p(rm0 - nm0), corr1 = exp2p(rm1 - nm1);
        rm0 = nm0; rm1 = nm1;

        float s0 = 0.f, s1 = 0.f;
#pragma unroll
        for (int nt = 0; nt < 8; nt++) {
            const float p0 = exp2p(sf[nt][0] - nm0);
            const float p1 = exp2p(sf[nt][1] - nm0);
            const float p2 = exp2p(sf[nt][2] - nm1);
            const float p3 = exp2p(sf[nt][3] - nm1);
            s0 += p0 + p1;  s1 += p2 + p3;
            const int col = nt * 8 + 2 * c4;
            const int u   = col >> 2;
            const int wd  = col & 3;
            Pw[(r4    ) * 64 + ((u ^ r4) << 2) + wd    ] = f2tf32f(p0);
            Pw[(r4    ) * 64 + ((u ^ r4) << 2) + wd + 1] = f2tf32f(p1);
            Pw[(r4 + 8) * 64 + ((u ^ r4) << 2) + wd    ] = f2tf32f(p2);
            Pw[(r4 + 8) * 64 + ((u ^ r4) << 2) + wd + 1] = f2tf32f(p3);
        }
        s0 += __shfl_xor_sync(0xffffffffu, s0, 1);
        s0 += __shfl_xor_sync(0xffffffffu, s0, 2);
        s1 += __shfl_xor_sync(0xffffffffu, s1, 1);
        s1 += __shfl_xor_sync(0xffffffffu, s1, 2);
        rl0 = rl0 * corr0 + s0;
        rl1 = rl1 * corr1 + s1;

#pragma unroll
        for (int dt = 0; dt < 8; dt++) {
            oacc[dt][0] *= corr0; oacc[dt][1] *= corr0;
            oacc[dt][2] *= corr1; oacc[dt][3] *= corr1;
        }
        __syncwarp();

#pragma unroll
        for (int ks = 0; ks < 8; ks++) {
            unsigned pf[4];
            ldsm4(pf[0], pf[1], pf[2], pf[3], sP + rowb + colb[ks]);
#pragma unroll
            for (int g = 0; g < 4; g++) {
                unsigned d0, d1, d2, d3;
                ldsm4(d0, d1, d2, d3, va + g * 4096 + rowb + colb[ks]);
                unsigned b0[2] = { d0, d2 };
                unsigned b1[2] = { d1, d3 };
                mma_tf32(oacc[2*g    ], pf, b0);
                mma_tf32(oacc[2*g + 1], pf, b1);
            }
        }
        __syncwarp();
    }

    const float inv0 = 1.f / rl0;
    const float inv1 = 1.f / rl1;
    const int bb = bh >> 4;
    const int h  = bh & 15;
    const size_t rg = (size_t)(bb * TSEQ + qt * 64 + w * 16 + r4);
    float* O0 = g_attn + rg * D_MODEL + h * HD;
    float* O1 = O0 + 8 * D_MODEL;
#pragma unroll
    for (int dt = 0; dt < 8; dt++) {
        const int dim = dt * 8 + 2 * c4;
        *(float2*)(O0 + dim) = make_float2(f2tf32f(oacc[dt][0] * inv0),
                                           f2tf32f(oacc[dt][1] * inv0));
        *(float2*)(O1 + dim) = make_float2(f2tf32f(oacc[dt][2] * inv1),
                                           f2tf32f(oacc[dt][3] * inv1));
    }
}

// ---------------------------------------------------------------------------
extern "C" void kernel_launch(void* const* d_in, const int* in_sizes, int n_in,
                              void* d_out, int out_size)
{
    const float* x  = (const float*)d_in[0];
    const float* Wq = (const float*)d_in[1];
    const float* Wk = (const float*)d_in[2];
    const float* Wv = (const float*)d_in[3];
    const float* Wo = (const float*)d_in[4];
    float* out = (float*)d_out;

    const int gemm_smem = GEMM_SMEM_BYTES;               // 147456
    const int attn_smem = ATTN_SMEM_BYTES;               // 114688
    cudaFuncSetAttribute(gemm_qkv_tc, cudaFuncAttributeMaxDynamicSharedMemorySize, gemm_smem);
    cudaFuncSetAttribute(gemm_o_tc,   cudaFuncAttributeMaxDynamicSharedMemorySize, gemm_smem);
    cudaFuncSetAttribute(attn_tc,     cudaFuncAttributeMaxDynamicSharedMemorySize, attn_smem);

    cvt_in<<<8192, 256>>>((const float4*)x, (const float4*)Wq, (const float4*)Wk,
                          (const float4*)Wv, (const float4*)Wo);

    dim3 gqkv(1024 / 256, MROWS / 128, 3);
    gemm_qkv_tc<<<gqkv, 256, gemm_smem>>>();

    dim3 gattn(TSEQ / 64, BATCH * NHEADS);
    attn_tc<<<gattn, 128, attn_smem>>>();

    dim3 go(1024 / 256, MROWS / 128);
    gemm_o_tc<<<go, 256, gemm_smem>>>(out);
}

// round 12
// speedup vs baseline: 1.1465x; 1.0105x over previous
#include <cuda_runtime.h>
#include <cstddef>

#define D_MODEL 1024
#define NHEADS  16
#define HD      64
#define BATCH   2
#define TSEQ    2048
#define MROWS   (BATCH*TSEQ)   /* 4096 */

// Scratch (device globals). All hold tf32 bit patterns (valid fp32, low 13
// mantissa bits zero) except d_out which gets full fp32.
__device__ float g_xc[(size_t)MROWS * D_MODEL];     // x rounded to tf32
__device__ float g_wq[(size_t)D_MODEL * D_MODEL];
__device__ float g_wk[(size_t)D_MODEL * D_MODEL];
__device__ float g_wv[(size_t)D_MODEL * D_MODEL];
__device__ float g_wo[(size_t)D_MODEL * D_MODEL];
__device__ float g_q[(size_t)MROWS * D_MODEL];      // [B,H,T,64]
__device__ float g_k[(size_t)MROWS * D_MODEL];      // [B,H,T,64]
__device__ float g_v[(size_t)MROWS * D_MODEL];      // TRANSPOSED [B,H,64,T]
__device__ float g_attn[(size_t)MROWS * D_MODEL];   // [B,T,1024]

// ---------------------------------------------------------------------------
// helpers
// ---------------------------------------------------------------------------
__device__ __forceinline__ unsigned f2tf32(float x) {
    unsigned r; asm("cvt.rna.tf32.f32 %0, %1;" : "=r"(r) : "f"(x)); return r;
}
__device__ __forceinline__ float f2tf32f(float x) { return __uint_as_float(f2tf32(x)); }

__device__ __forceinline__ void mma_tf32(float c[4], const unsigned a[4], const unsigned b[2]) {
    asm volatile(
        "mma.sync.aligned.m16n8k8.row.col.f32.tf32.tf32.f32 "
        "{%0,%1,%2,%3}, {%4,%5,%6,%7}, {%8,%9}, {%0,%1,%2,%3};"
        : "+f"(c[0]), "+f"(c[1]), "+f"(c[2]), "+f"(c[3])
        : "r"(a[0]), "r"(a[1]), "r"(a[2]), "r"(a[3]), "r"(b[0]), "r"(b[1]));
}
__device__ __forceinline__ void ldsm4(unsigned &d0, unsigned &d1, unsigned &d2, unsigned &d3,
                                      unsigned addr) {
    asm volatile("ldmatrix.sync.aligned.m8n8.x4.shared.b16 {%0,%1,%2,%3}, [%4];"
                 : "=r"(d0), "=r"(d1), "=r"(d2), "=r"(d3) : "r"(addr));
}
__device__ __forceinline__ void cpa16(unsigned dst, const void* src) {
    asm volatile("cp.async.cg.shared.global [%0], [%1], 16;" :: "r"(dst), "l"(src));
}
__device__ __forceinline__ void cpcommit() { asm volatile("cp.async.commit_group;"); }
template<int N> __device__ __forceinline__ void cpwait() {
    asm volatile("cp.async.wait_group %0;" :: "n"(N) : "memory");
}

// fast exp2 for x <= 0 (FMA pipe, no MUFU)
__device__ __forceinline__ float exp2p(float x) {
    x = fmaxf(x, -126.f);
    float z = x + 12582912.0f;
    int   n = __float_as_int(z) - 0x4B400000;
    float f = x - (z - 12582912.0f);
    float p = 0.0096181291f;
    p = fmaf(p, f, 0.0555041087f);
    p = fmaf(p, f, 0.2402265069f);
    p = fmaf(p, f, 0.6931471806f);
    p = fmaf(p, f, 1.0f);
    return __int_as_float(__float_as_int(p) + (n << 23));
}

// ---------------------------------------------------------------------------
// input pre-conversion: rna-round x and the 4 weight matrices to tf32
// ---------------------------------------------------------------------------
__global__ __launch_bounds__(256) void cvt_in(
    const float4* __restrict__ x,
    const float4* __restrict__ wq, const float4* __restrict__ wk,
    const float4* __restrict__ wv, const float4* __restrict__ wo)
{
    const size_t i = (size_t)blockIdx.x * 256 + threadIdx.x;   // 0 .. 2M-1
    const float4* src; float4* dst;
    if (i < (1u << 20)) {
        src = x + i;  dst = (float4*)g_xc + i;
    } else {
        size_t j = i - (1u << 20);
        int ww = (int)(j >> 18);
        size_t o = j & ((1u << 18) - 1);
        const float4* s = (ww == 0) ? wq : (ww == 1) ? wk : (ww == 2) ? wv : wo;
        float4*       d = (ww == 0) ? (float4*)g_wq : (ww == 1) ? (float4*)g_wk
                                    : (ww == 2) ? (float4*)g_wv : (float4*)g_wo;
        src = s + o; dst = d + o;
    }
    float4 v = *src;
    float4 r;
    r.x = f2tf32f(v.x); r.y = f2tf32f(v.y); r.z = f2tf32f(v.z); r.w = f2tf32f(v.w);
    *dst = r;
}

// ---------------------------------------------------------------------------
// tf32 GEMM: C = A @ W^T, inputs already tf32. Block tile 128x128, k-chunk 32,
// 4 warps (128 threads) with 64x64 warp tiles (2 x 2). 3-stage cp.async,
// XOR-swizzled smem, ldmatrix.x4, no cvt in mainloop. 2 CTAs/SM.
// EPI: 0 plain fp32; 1 Q/K permute ([B,H,T,64], tf32); 2 V transpose
// ([B,H,64,T], tf32).
// ---------------------------------------------------------------------------
#define GSA (128*32)                    /* A floats per stage */
#define GSB (128*32)                    /* B floats per stage */
#define GEMM_SMEM_BYTES ((GSA+GSB)*3*4) /* 98304 */

template <int EPI>
__device__ __forceinline__ void gemm_body(const float* __restrict__ A,
                                          const float* __restrict__ W,
                                          float* __restrict__ C)
{
    extern __shared__ float gsm[];
    const unsigned sA = (unsigned)__cvta_generic_to_shared(gsm);
    const unsigned sB = sA + 3 * GSA * 4;

    const int tid  = threadIdx.x;
    const int lane = tid & 31;
    const int warp = tid >> 5;           // 0..3
    const int wm   = warp >> 1;          // 0..1  (64 rows)
    const int wn   = warp & 1;           // 0..1  (64 cols)
    const int bx   = blockIdx.x;
    const int by   = blockIdx.y;

    const int lr16 = lane & 15;
    const int lhi  = lane >> 4;
    const int lx7  = lane & 7;
    const int r4   = lane >> 2;
    const int c4   = lane & 3;

    const int fu = tid & 7;              // float4 unit within 32-float row
    const int fr = tid >> 3;             // 0..15
    const float* Ag = A + (size_t)(by * 128) * 1024 + fu * 4;
    const float* Wg = W + (size_t)(bx * 128) * 1024 + fu * 4;

    const unsigned a_row = (unsigned)(wm * 64 + lr16) * 128;
    const unsigned b_row = (unsigned)(wn * 64 + lr16) * 128;
    unsigned colb[4];
#pragma unroll
    for (int ks = 0; ks < 4; ks++) colb[ks] = (unsigned)(((ks * 2 + lhi) ^ lx7) * 16);

    float acc[4][8][4];
#pragma unroll
    for (int mt = 0; mt < 4; mt++)
#pragma unroll
        for (int nt = 0; nt < 8; nt++)
#pragma unroll
            for (int e = 0; e < 4; e++) acc[mt][nt][e] = 0.f;

#pragma unroll
    for (int pk = 0; pk < 2; pk++) {
        const unsigned ab = sA + pk * GSA * 4;
        const unsigned bb = sB + pk * GSB * 4;
#pragma unroll
        for (int i = 0; i < 8; i++) {
            const int r = fr + i * 16;
            const unsigned off = (unsigned)((r * 8 + (fu ^ (r & 7))) * 16);
            cpa16(ab + off, Ag + (size_t)r * 1024 + pk * 32);
            cpa16(bb + off, Wg + (size_t)r * 1024 + pk * 32);
        }
        cpcommit();
    }

    for (int ki = 0; ki < 32; ki++) {
        cpwait<1>();
        __syncthreads();

        if (ki + 2 < 32) {
            const int st = (ki + 2) % 3;
            const unsigned ab = sA + st * GSA * 4;
            const unsigned bb = sB + st * GSB * 4;
#pragma unroll
            for (int i = 0; i < 8; i++) {
                const int r = fr + i * 16;
                const unsigned off = (unsigned)((r * 8 + (fu ^ (r & 7))) * 16);
                cpa16(ab + off, Ag + (size_t)r * 1024 + (ki + 2) * 32);
                cpa16(bb + off, Wg + (size_t)r * 1024 + (ki + 2) * 32);
            }
        }
        cpcommit();

        const int s = ki % 3;
        const unsigned ab = sA + s * GSA * 4;
        const unsigned bb = sB + s * GSB * 4;
#pragma unroll
        for (int ks = 0; ks < 4; ks++) {
            unsigned af[4][4];
#pragma unroll
            for (int mt = 0; mt < 4; mt++)
                ldsm4(af[mt][0], af[mt][1], af[mt][2], af[mt][3],
                      ab + a_row + mt * 2048 + colb[ks]);
            unsigned bf[4][4];
#pragma unroll
            for (int n2 = 0; n2 < 4; n2++)
                ldsm4(bf[n2][0], bf[n2][1], bf[n2][2], bf[n2][3],
                      bb + b_row + n2 * 2048 + colb[ks]);
#pragma unroll
            for (int mt = 0; mt < 4; mt++)
#pragma unroll
                for (int nt = 0; nt < 8; nt++) {
                    const int n2 = nt >> 1, sub = nt & 1;
                    unsigned bq[2] = { bf[n2][sub], bf[n2][sub + 2] };
                    mma_tf32(acc[mt][nt], af[mt], bq);
                }
        }
    }

#pragma unroll
    for (int mt = 0; mt < 4; mt++) {
        const int row0 = by * 128 + wm * 64 + mt * 16 + r4;
#pragma unroll
        for (int nt = 0; nt < 8; nt++) {
            const int col = bx * 128 + wn * 64 + nt * 8 + 2 * c4;
            if (EPI == 0) {
                *(float2*)&C[(size_t)row0 * 1024 + col] =
                    make_float2(acc[mt][nt][0], acc[mt][nt][1]);
                *(float2*)&C[(size_t)(row0 + 8) * 1024 + col] =
                    make_float2(acc[mt][nt][2], acc[mt][nt][3]);
            } else if (EPI == 1) {
                const int h = col >> 6, d = col & 63;
                const int b2 = row0 >> 11, t0 = row0 & 2047;
                float* base = C + (((size_t)(b2 * NHEADS + h)) * TSEQ) * HD + d;
                *(float2*)(base + (size_t)t0 * HD) =
                    make_float2(f2tf32f(acc[mt][nt][0]), f2tf32f(acc[mt][nt][1]));
                *(float2*)(base + (size_t)(t0 + 8) * HD) =
                    make_float2(f2tf32f(acc[mt][nt][2]), f2tf32f(acc[mt][nt][3]));
            } else {
                const int h = col >> 6, d = col & 63;
                const int b2 = row0 >> 11, t0 = row0 & 2047;
                float* base = C + ((size_t)(b2 * NHEADS + h) * HD + d) * TSEQ;
                base[t0]            = f2tf32f(acc[mt][nt][0]);
                base[TSEQ + t0]     = f2tf32f(acc[mt][nt][1]);
                base[t0 + 8]        = f2tf32f(acc[mt][nt][2]);
                base[TSEQ + t0 + 8] = f2tf32f(acc[mt][nt][3]);
            }
        }
    }
}

__global__ __launch_bounds__(128, 2) void gemm_qkv_tc() {
    if (blockIdx.z == 0)      gemm_body<1>(g_xc, g_wq, g_q);
    else if (blockIdx.z == 1) gemm_body<1>(g_xc, g_wk, g_k);
    else                      gemm_body<2>(g_xc, g_wv, g_v);
}
__global__ __launch_bounds__(128, 2) void gemm_o_tc(float* __restrict__ out) {
    gemm_body<0>(g_attn, g_wo, out);
}

// ---------------------------------------------------------------------------
// Flash attention, tf32, causal. 128 threads (4 warps), 64 q rows per block.
// 2-stage cp.async K/V pipeline (80KB smem -> 2 CTAs/SM).
// ---------------------------------------------------------------------------
#define AT 4096                                      /* floats per 64x64 tile */
#define ATTN_SMEM_BYTES ((4*AT + 4*16*64) * 4)       /* 81920 */

__global__ __launch_bounds__(128, 2) void attn_tc() {
    extern __shared__ float asm_[];
    float* Pbuf = asm_ + 4 * AT;
    const unsigned sK = (unsigned)__cvta_generic_to_shared(asm_);
    const unsigned sV = sK + 2 * AT * 4;

    const int tid  = threadIdx.x;
    const int lane = tid & 31;
    const int w    = tid >> 5;
    const int r4   = lane >> 2;
    const int c4   = lane & 3;
    const int lr16 = lane & 15;
    const int lhi  = lane >> 4;
    const int lx7  = lane & 7;
    const int bh   = blockIdx.y;
    const int qt   = (int)gridDim.x - 1 - (int)blockIdx.x;   // heavy first

    const float* Kg = g_k + (size_t)bh * TSEQ * HD;   // [t][d]
    const float* Vg = g_v + (size_t)bh * HD * TSEQ;   // [d][t]

    float* Pw = Pbuf + w * 16 * 64;
    const unsigned sP = (unsigned)__cvta_generic_to_shared(Pw);

    const int fu = tid & 15;
    const int fr = tid >> 4;

    unsigned qf[8][4];
    {
        const float* Qb = g_q + ((size_t)bh * TSEQ + qt * 64 + w * 16) * HD;
#pragma unroll
        for (int ks = 0; ks < 8; ks++) {
            qf[ks][0] = __float_as_uint(Qb[(r4    ) * HD + ks*8 + c4    ]);
            qf[ks][1] = __float_as_uint(Qb[(r4 + 8) * HD + ks*8 + c4    ]);
            qf[ks][2] = __float_as_uint(Qb[(r4    ) * HD + ks*8 + c4 + 4]);
            qf[ks][3] = __float_as_uint(Qb[(r4 + 8) * HD + ks*8 + c4 + 4]);
        }
    }

    unsigned colb[8];
#pragma unroll
    for (int ks = 0; ks < 8; ks++) colb[ks] = (unsigned)(((ks * 2 + lhi) ^ lx7) * 16);
    const unsigned rowb = (unsigned)lr16 * 256;

    float oacc[8][4];
#pragma unroll
    for (int dt = 0; dt < 8; dt++)
#pragma unroll
        for (int e = 0; e < 4; e++) oacc[dt][e] = 0.f;
    float rm0 = -1e30f, rm1 = -1e30f, rl0 = 0.f, rl1 = 0.f;

    const int rowL0 = w * 16 + r4;
    const int rowL1 = rowL0 + 8;
    const float SC2 = 0.1803368801f;      // (1/8)*log2(e)

    // prologue: fill tiles 0 and 1 into stages 0,1
#pragma unroll
    for (int pk = 0; pk < 2; pk++) {
        if (pk <= qt) {
            const unsigned ka = sK + pk * AT * 4;
            const unsigned va = sV + pk * AT * 4;
#pragma unroll
            for (int i = 0; i < 8; i++) {
                const int r = fr + i * 8;
                const unsigned off = (unsigned)((r * 16 + (fu ^ (r & 7))) * 16);
                cpa16(ka + off, Kg + (size_t)(pk * 64 + r) * HD + fu * 4);
                cpa16(va + off, Vg + (size_t)r * TSEQ + pk * 64 + fu * 4);
            }
        }
        cpcommit();
    }

    for (int kt = 0; kt <= qt; kt++) {
        cpwait<1>();
        __syncthreads();

        const int s = kt & 1;
        const unsigned ka = sK + s * AT * 4;
        const unsigned va = sV + s * AT * 4;

        // S = Q @ K^T (16 x 64 per warp)
        float sf[8][4];
#pragma unroll
        for (int nt = 0; nt < 8; nt++)
#pragma unroll
            for (int e = 0; e < 4; e++) sf[nt][e] = 0.f;
#pragma unroll
        for (int ks = 0; ks < 8; ks++) {
#pragma unroll
            for (int g = 0; g < 4; g++) {
                unsigned d0, d1, d2, d3;
                ldsm4(d0, d1, d2, d3, ka + g * 4096 + rowb + colb[ks]);
                unsigned b0[2] = { d0, d2 };
                unsigned b1[2] = { d1, d3 };
                mma_tf32(sf[2*g    ], qf[ks], b0);
                mma_tf32(sf[2*g + 1], qf[ks], b1);
            }
        }

        const bool diag = (kt == qt);
#pragma unroll
        for (int nt = 0; nt < 8; nt++) {
            sf[nt][0] *= SC2; sf[nt][1] *= SC2; sf[nt][2] *= SC2; sf[nt][3] *= SC2;
            if (diag) {
                const int kc = nt * 8 + 2 * c4;
                if (kc     > rowL0) sf[nt][0] = -1e30f;
                if (kc + 1 > rowL0) sf[nt][1] = -1e30f;
                if (kc     > rowL1) sf[nt][2] = -1e30f;
                if (kc + 1 > rowL1) sf[nt][3] = -1e30f;
            }
        }

        float mx0 = -1e30f, mx1 = -1e30f;
#pragma unroll
        for (int nt = 0; nt < 8; nt++) {
            mx0 = fmaxf(mx0, fmaxf(sf[nt][0], sf[nt][1]));
            mx1 = fmaxf(mx1, fmaxf(sf[nt][2], sf[nt][3]));
        }
        mx0 = fmaxf(mx0, __shfl_xor_sync(0xffffffffu, mx0, 1));
        mx0 = fmaxf(mx0, __shfl_xor_sync(0xffffffffu, mx0, 2));
        mx1 = fmaxf(mx1, __shfl_xor_sync(0xffffffffu, mx1, 1));
        mx1 = fmaxf(mx1, __shfl_xor_sync(0xffffffffu, mx1, 2));

        const float nm0 = fmaxf(rm0, mx0), nm1 = fmaxf(rm1, mx1);
        const float corr0 = exp2p(rm0 - nm0), corr1 = exp2p(rm1 - nm1);
        rm0 = nm0; rm1 = nm1;

        float s0 = 0.f, s1 = 0.f;
#pragma unroll
        for (int nt = 0; nt < 8; nt++) {
            const float p0 = exp2p(sf[nt][0] - nm0);
            const float p1 = exp2p(sf[nt][1] - nm0);
            const float p2 = exp2p(sf[nt][2] - nm1);
            const float p3 = exp2p(sf[nt][3] - nm1);
            s0 += p0 + p1;  s1 += p2 + p3;
            const int col = nt * 8 + 2 * c4;
            const int u   = col >> 2;
            const int wd  = col & 3;
            Pw[(r4    ) * 64 + ((u ^ r4) << 2) + wd    ] = f2tf32f(p0);
            Pw[(r4    ) * 64 + ((u ^ r4) << 2) + wd + 1] = f2tf32f(p1);
            Pw[(r4 + 8) * 64 + ((u ^ r4) << 2) + wd    ] = f2tf32f(p2);
            Pw[(r4 + 8) * 64 + ((u ^ r4) << 2) + wd + 1] = f2tf32f(p3);
        }
        s0 += __shfl_xor_sync(0xffffffffu, s0, 1);
        s0 += __shfl_xor_sync(0xffffffffu, s0, 2);
        s1 += __shfl_xor_sync(0xffffffffu, s1, 1);
        s1 += __shfl_xor_sync(0xffffffffu, s1, 2);
        rl0 = rl0 * corr0 + s0;
        rl1 = rl1 * corr1 + s1;

#pragma unroll
        for (int dt = 0; dt < 8; dt++) {
            oacc[dt][0] *= corr0; oacc[dt][1] *= corr0;
            oacc[dt][2] *= corr1; oacc[dt][3] *= corr1;
        }
        __syncwarp();

        // O += P @ V^T
#pragma unroll
        for (int ks = 0; ks < 8; ks++) {
            unsigned pf[4];
            ldsm4(pf[0], pf[1], pf[2], pf[3], sP + rowb + colb[ks]);
#pragma unroll
            for (int g = 0; g < 4; g++) {
                unsigned d0, d1, d2, d3;
                ldsm4(d0, d1, d2, d3, va + g * 4096 + rowb + colb[ks]);
                unsigned b0[2] = { d0, d2 };
                unsigned b1[2] = { d1, d3 };
                mma_tf32(oacc[2*g    ], pf, b0);
                mma_tf32(oacc[2*g + 1], pf, b1);
            }
        }

        // all warps done reading stage s before refilling it next iteration
        __syncthreads();
        if (kt + 2 <= qt) {
            const unsigned ka2 = sK + s * AT * 4;   // stage (kt+2)&1 == s
            const unsigned va2 = sV + s * AT * 4;
#pragma unroll
            for (int i = 0; i < 8; i++) {
                const int r = fr + i * 8;
                const unsigned off = (unsigned)((r * 16 + (fu ^ (r & 7))) * 16);
                cpa16(ka2 + off, Kg + (size_t)((kt + 2) * 64 + r) * HD + fu * 4);
                cpa16(va2 + off, Vg + (size_t)r * TSEQ + (kt + 2) * 64 + fu * 4);
            }
        }
        cpcommit();
    }

    const float inv0 = 1.f / rl0;
    const float inv1 = 1.f / rl1;
    const int bb = bh >> 4;
    const int h  = bh & 15;
    const size_t rg = (size_t)(bb * TSEQ + qt * 64 + w * 16 + r4);
    float* O0 = g_attn + rg * D_MODEL + h * HD;
    float* O1 = O0 + 8 * D_MODEL;
#pragma unroll
    for (int dt = 0; dt < 8; dt++) {
        const int dim = dt * 8 + 2 * c4;
        *(float2*)(O0 + dim) = make_float2(f2tf32f(oacc[dt][0] * inv0),
                                           f2tf32f(oacc[dt][1] * inv0));
        *(float2*)(O1 + dim) = make_float2(f2tf32f(oacc[dt][2] * inv1),
                                           f2tf32f(oacc[dt][3] * inv1));
    }
}

// ---------------------------------------------------------------------------
extern "C" void kernel_launch(void* const* d_in, const int* in_sizes, int n_in,
                              void* d_out, int out_size)
{
    const float* x  = (const float*)d_in[0];
    const float* Wq = (const float*)d_in[1];
    const float* Wk = (const float*)d_in[2];
    const float* Wv = (const float*)d_in[3];
    const float* Wo = (const float*)d_in[4];
    float* out = (float*)d_out;

    const int gemm_smem = GEMM_SMEM_BYTES;               // 98304
    const int attn_smem = ATTN_SMEM_BYTES;               // 81920
    cudaFuncSetAttribute(gemm_qkv_tc, cudaFuncAttributeMaxDynamicSharedMemorySize, gemm_smem);
    cudaFuncSetAttribute(gemm_o_tc,   cudaFuncAttributeMaxDynamicSharedMemorySize, gemm_smem);
    cudaFuncSetAttribute(attn_tc,     cudaFuncAttributeMaxDynamicSharedMemorySize, attn_smem);

    cvt_in<<<8192, 256>>>((const float4*)x, (const float4*)Wq, (const float4*)Wk,
                          (const float4*)Wv, (const float4*)Wo);

    dim3 gqkv(1024 / 128, MROWS / 128, 3);
    gemm_qkv_tc<<<gqkv, 128, gemm_smem>>>();

    dim3 gattn(TSEQ / 64, BATCH * NHEADS);
    attn_tc<<<gattn, 128, attn_smem>>>();

    dim3 go(1024 / 128, MROWS / 128);
    gemm_o_tc<<<go, 128, gemm_smem>>>(out);
}

// round 13
// speedup vs baseline: 1.1528x; 1.0055x over previous
#include <cuda_runtime.h>
#include <cstddef>

#define D_MODEL 1024
#define NHEADS  16
#define HD      64
#define BATCH   2
#define TSEQ    2048
#define MROWS   (BATCH*TSEQ)   /* 4096 */

// Scratch (device globals). All hold tf32 bit patterns (valid fp32, low 13
// mantissa bits zero) except d_out which gets full fp32.
__device__ float g_xc[(size_t)MROWS * D_MODEL];     // x rounded to tf32
__device__ float g_wq[(size_t)D_MODEL * D_MODEL];
__device__ float g_wk[(size_t)D_MODEL * D_MODEL];
__device__ float g_wv[(size_t)D_MODEL * D_MODEL];
__device__ float g_wo[(size_t)D_MODEL * D_MODEL];
__device__ float g_q[(size_t)MROWS * D_MODEL];      // [B,H,T,64]
__device__ float g_k[(size_t)MROWS * D_MODEL];      // [B,H,T,64]
__device__ float g_v[(size_t)MROWS * D_MODEL];      // TRANSPOSED [B,H,64,T]
__device__ float g_attn[(size_t)MROWS * D_MODEL];   // [B,T,1024]

// ---------------------------------------------------------------------------
// helpers
// ---------------------------------------------------------------------------
__device__ __forceinline__ unsigned f2tf32(float x) {
    unsigned r; asm("cvt.rna.tf32.f32 %0, %1;" : "=r"(r) : "f"(x)); return r;
}
__device__ __forceinline__ float f2tf32f(float x) { return __uint_as_float(f2tf32(x)); }

__device__ __forceinline__ void mma_tf32(float c[4], const unsigned a[4], const unsigned b[2]) {
    asm volatile(
        "mma.sync.aligned.m16n8k8.row.col.f32.tf32.tf32.f32 "
        "{%0,%1,%2,%3}, {%4,%5,%6,%7}, {%8,%9}, {%0,%1,%2,%3};"
        : "+f"(c[0]), "+f"(c[1]), "+f"(c[2]), "+f"(c[3])
        : "r"(a[0]), "r"(a[1]), "r"(a[2]), "r"(a[3]), "r"(b[0]), "r"(b[1]));
}
__device__ __forceinline__ void ldsm4(unsigned &d0, unsigned &d1, unsigned &d2, unsigned &d3,
                                      unsigned addr) {
    asm volatile("ldmatrix.sync.aligned.m8n8.x4.shared.b16 {%0,%1,%2,%3}, [%4];"
                 : "=r"(d0), "=r"(d1), "=r"(d2), "=r"(d3) : "r"(addr));
}
__device__ __forceinline__ void cpa16(unsigned dst, const void* src) {
    asm volatile("cp.async.cg.shared.global [%0], [%1], 16;" :: "r"(dst), "l"(src));
}
__device__ __forceinline__ void cpcommit() { asm volatile("cp.async.commit_group;"); }
template<int N> __device__ __forceinline__ void cpwait() {
    asm volatile("cp.async.wait_group %0;" :: "n"(N) : "memory");
}

// fast exp2 for x <= 0 (FMA pipe, no MUFU)
__device__ __forceinline__ float exp2p(float x) {
    x = fmaxf(x, -126.f);
    float z = x + 12582912.0f;
    int   n = __float_as_int(z) - 0x4B400000;
    float f = x - (z - 12582912.0f);
    float p = 0.0096181291f;
    p = fmaf(p, f, 0.0555041087f);
    p = fmaf(p, f, 0.2402265069f);
    p = fmaf(p, f, 0.6931471806f);
    p = fmaf(p, f, 1.0f);
    return __int_as_float(__float_as_int(p) + (n << 23));
}

// ---------------------------------------------------------------------------
// input pre-conversion: rna-round x and the 4 weight matrices to tf32
// ---------------------------------------------------------------------------
__global__ __launch_bounds__(256) void cvt_in(
    const float4* __restrict__ x,
    const float4* __restrict__ wq, const float4* __restrict__ wk,
    const float4* __restrict__ wv, const float4* __restrict__ wo)
{
    const size_t i = (size_t)blockIdx.x * 256 + threadIdx.x;   // 0 .. 2M-1
    const float4* src; float4* dst;
    if (i < (1u << 20)) {
        src = x + i;  dst = (float4*)g_xc + i;
    } else {
        size_t j = i - (1u << 20);
        int ww = (int)(j >> 18);
        size_t o = j & ((1u << 18) - 1);
        const float4* s = (ww == 0) ? wq : (ww == 1) ? wk : (ww == 2) ? wv : wo;
        float4*       d = (ww == 0) ? (float4*)g_wq : (ww == 1) ? (float4*)g_wk
                                    : (ww == 2) ? (float4*)g_wv : (float4*)g_wo;
        src = s + o; dst = d + o;
    }
    float4 v = *src;
    float4 r;
    r.x = f2tf32f(v.x); r.y = f2tf32f(v.y); r.z = f2tf32f(v.z); r.w = f2tf32f(v.w);
    *dst = r;
}

// ---------------------------------------------------------------------------
// tf32 GEMM: C = A @ W^T, inputs already tf32. Block tile 128x128, k-chunk 32,
// 4 warps (128 threads) with 64x64 warp tiles (2 x 2). 2-stage cp.async
// (64KB smem -> 3 CTAs/SM), XOR-swizzled smem, ldmatrix.x4, no cvt in loop.
// EPI: 0 plain fp32; 1 Q/K permute ([B,H,T,64], tf32); 2 V transpose
// ([B,H,64,T], tf32).
// ---------------------------------------------------------------------------
#define GSA (128*32)                    /* A floats per stage */
#define GSB (128*32)                    /* B floats per stage */
#define GEMM_SMEM_BYTES ((GSA+GSB)*2*4) /* 65536 */

template <int EPI>
__device__ __forceinline__ void gemm_body(const float* __restrict__ A,
                                          const float* __restrict__ W,
                                          float* __restrict__ C)
{
    extern __shared__ float gsm[];
    const unsigned sA = (unsigned)__cvta_generic_to_shared(gsm);
    const unsigned sB = sA + 2 * GSA * 4;

    const int tid  = threadIdx.x;
    const int lane = tid & 31;
    const int warp = tid >> 5;           // 0..3
    const int wm   = warp >> 1;          // 0..1  (64 rows)
    const int wn   = warp & 1;           // 0..1  (64 cols)
    const int bx   = blockIdx.x;
    const int by   = blockIdx.y;

    const int lr16 = lane & 15;
    const int lhi  = lane >> 4;
    const int lx7  = lane & 7;
    const int r4   = lane >> 2;
    const int c4   = lane & 3;

    const int fu = tid & 7;              // float4 unit within 32-float row
    const int fr = tid >> 3;             // 0..15
    const float* Ag = A + (size_t)(by * 128) * 1024 + fu * 4;
    const float* Wg = W + (size_t)(bx * 128) * 1024 + fu * 4;

    const unsigned a_row = (unsigned)(wm * 64 + lr16) * 128;
    const unsigned b_row = (unsigned)(wn * 64 + lr16) * 128;
    unsigned colb[4];
#pragma unroll
    for (int ks = 0; ks < 4; ks++) colb[ks] = (unsigned)(((ks * 2 + lhi) ^ lx7) * 16);

    float acc[4][8][4];
#pragma unroll
    for (int mt = 0; mt < 4; mt++)
#pragma unroll
        for (int nt = 0; nt < 8; nt++)
#pragma unroll
            for (int e = 0; e < 4; e++) acc[mt][nt][e] = 0.f;

    // prologue: fill stages 0,1 with k-chunks 0,1
#pragma unroll
    for (int pk = 0; pk < 2; pk++) {
        const unsigned ab = sA + pk * GSA * 4;
        const unsigned bb = sB + pk * GSB * 4;
#pragma unroll
        for (int i = 0; i < 8; i++) {
            const int r = fr + i * 16;
            const unsigned off = (unsigned)((r * 8 + (fu ^ (r & 7))) * 16);
            cpa16(ab + off, Ag + (size_t)r * 1024 + pk * 32);
            cpa16(bb + off, Wg + (size_t)r * 1024 + pk * 32);
        }
        cpcommit();
    }

    for (int ki = 0; ki < 32; ki++) {
        cpwait<1>();
        __syncthreads();

        const int s = ki & 1;
        const unsigned ab = sA + s * GSA * 4;
        const unsigned bb = sB + s * GSB * 4;
#pragma unroll
        for (int ks = 0; ks < 4; ks++) {
            unsigned af[4][4];
#pragma unroll
            for (int mt = 0; mt < 4; mt++)
                ldsm4(af[mt][0], af[mt][1], af[mt][2], af[mt][3],
                      ab + a_row + mt * 2048 + colb[ks]);
            unsigned bf[4][4];
#pragma unroll
            for (int n2 = 0; n2 < 4; n2++)
                ldsm4(bf[n2][0], bf[n2][1], bf[n2][2], bf[n2][3],
                      bb + b_row + n2 * 2048 + colb[ks]);
#pragma unroll
            for (int mt = 0; mt < 4; mt++)
#pragma unroll
                for (int nt = 0; nt < 8; nt++) {
                    const int n2 = nt >> 1, sub = nt & 1;
                    unsigned bq[2] = { bf[n2][sub], bf[n2][sub + 2] };
                    mma_tf32(acc[mt][nt], af[mt], bq);
                }
        }

        // all warps done reading stage s; refill it for chunk ki+2
        __syncthreads();
        if (ki + 2 < 32) {
#pragma unroll
            for (int i = 0; i < 8; i++) {
                const int r = fr + i * 16;
                const unsigned off = (unsigned)((r * 8 + (fu ^ (r & 7))) * 16);
                cpa16(ab + off, Ag + (size_t)r * 1024 + (ki + 2) * 32);
                cpa16(bb + off, Wg + (size_t)r * 1024 + (ki + 2) * 32);
            }
        }
        cpcommit();
    }

#pragma unroll
    for (int mt = 0; mt < 4; mt++) {
        const int row0 = by * 128 + wm * 64 + mt * 16 + r4;
#pragma unroll
        for (int nt = 0; nt < 8; nt++) {
            const int col = bx * 128 + wn * 64 + nt * 8 + 2 * c4;
            if (EPI == 0) {
                *(float2*)&C[(size_t)row0 * 1024 + col] =
                    make_float2(acc[mt][nt][0], acc[mt][nt][1]);
                *(float2*)&C[(size_t)(row0 + 8) * 1024 + col] =
                    make_float2(acc[mt][nt][2], acc[mt][nt][3]);
            } else if (EPI == 1) {
                const int h = col >> 6, d = col & 63;
                const int b2 = row0 >> 11, t0 = row0 & 2047;
                float* base = C + (((size_t)(b2 * NHEADS + h)) * TSEQ) * HD + d;
                *(float2*)(base + (size_t)t0 * HD) =
                    make_float2(f2tf32f(acc[mt][nt][0]), f2tf32f(acc[mt][nt][1]));
                *(float2*)(base + (size_t)(t0 + 8) * HD) =
                    make_float2(f2tf32f(acc[mt][nt][2]), f2tf32f(acc[mt][nt][3]));
            } else {
                const int h = col >> 6, d = col & 63;
                const int b2 = row0 >> 11, t0 = row0 & 2047;
                float* base = C + ((size_t)(b2 * NHEADS + h) * HD + d) * TSEQ;
                base[t0]            = f2tf32f(acc[mt][nt][0]);
                base[TSEQ + t0]     = f2tf32f(acc[mt][nt][1]);
                base[t0 + 8]        = f2tf32f(acc[mt][nt][2]);
                base[TSEQ + t0 + 8] = f2tf32f(acc[mt][nt][3]);
            }
        }
    }
}

__global__ __launch_bounds__(128, 3) void gemm_qkv_tc() {
    if (blockIdx.z == 0)      gemm_body<1>(g_xc, g_wq, g_q);
    else if (blockIdx.z == 1) gemm_body<1>(g_xc, g_wk, g_k);
    else                      gemm_body<2>(g_xc, g_wv, g_v);
}
__global__ __launch_bounds__(128, 3) void gemm_o_tc(float* __restrict__ out) {
    gemm_body<0>(g_attn, g_wo, out);
}

// ---------------------------------------------------------------------------
// Flash attention, tf32, causal. 128 threads (4 warps), 64 q rows per block.
// 2-stage cp.async K/V pipeline (80KB smem -> 2 CTAs/SM). Unchanged from R12.
// ---------------------------------------------------------------------------
#define AT 4096                                      /* floats per 64x64 tile */
#define ATTN_SMEM_BYTES ((4*AT + 4*16*64) * 4)       /* 81920 */

__global__ __launch_bounds__(128, 2) void attn_tc() {
    extern __shared__ float asm_[];
    float* Pbuf = asm_ + 4 * AT;
    const unsigned sK = (unsigned)__cvta_generic_to_shared(asm_);
    const unsigned sV = sK + 2 * AT * 4;

    const int tid  = threadIdx.x;
    const int lane = tid & 31;
    const int w    = tid >> 5;
    const int r4   = lane >> 2;
    const int c4   = lane & 3;
    const int lr16 = lane & 15;
    const int lhi  = lane >> 4;
    const int lx7  = lane & 7;
    const int bh   = blockIdx.y;
    const int qt   = (int)gridDim.x - 1 - (int)blockIdx.x;   // heavy first

    const float* Kg = g_k + (size_t)bh * TSEQ * HD;   // [t][d]
    const float* Vg = g_v + (size_t)bh * HD * TSEQ;   // [d][t]

    float* Pw = Pbuf + w * 16 * 64;
    const unsigned sP = (unsigned)__cvta_generic_to_shared(Pw);

    const int fu = tid & 15;
    const int fr = tid >> 4;

    unsigned qf[8][4];
    {
        const float* Qb = g_q + ((size_t)bh * TSEQ + qt * 64 + w * 16) * HD;
#pragma unroll
        for (int ks = 0; ks < 8; ks++) {
            qf[ks][0] = __float_as_uint(Qb[(r4    ) * HD + ks*8 + c4    ]);
            qf[ks][1] = __float_as_uint(Qb[(r4 + 8) * HD + ks*8 + c4    ]);
            qf[ks][2] = __float_as_uint(Qb[(r4    ) * HD + ks*8 + c4 + 4]);
            qf[ks][3] = __float_as_uint(Qb[(r4 + 8) * HD + ks*8 + c4 + 4]);
        }
    }

    unsigned colb[8];
#pragma unroll
    for (int ks = 0; ks < 8; ks++) colb[ks] = (unsigned)(((ks * 2 + lhi) ^ lx7) * 16);
    const unsigned rowb = (unsigned)lr16 * 256;

    float oacc[8][4];
#pragma unroll
    for (int dt = 0; dt < 8; dt++)
#pragma unroll
        for (int e = 0; e < 4; e++) oacc[dt][e] = 0.f;
    float rm0 = -1e30f, rm1 = -1e30f, rl0 = 0.f, rl1 = 0.f;

    const int rowL0 = w * 16 + r4;
    const int rowL1 = rowL0 + 8;
    const float SC2 = 0.1803368801f;      // (1/8)*log2(e)

    // prologue: fill tiles 0 and 1 into stages 0,1
#pragma unroll
    for (int pk = 0; pk < 2; pk++) {
        if (pk <= qt) {
            const unsigned ka = sK + pk * AT * 4;
            const unsigned va = sV + pk * AT * 4;
#pragma unroll
            for (int i = 0; i < 8; i++) {
                const int r = fr + i * 8;
                const unsigned off = (unsigned)((r * 16 + (fu ^ (r & 7))) * 16);
                cpa16(ka + off, Kg + (size_t)(pk * 64 + r) * HD + fu * 4);
                cpa16(va + off, Vg + (size_t)r * TSEQ + pk * 64 + fu * 4);
            }
        }
        cpcommit();
    }

    for (int kt = 0; kt <= qt; kt++) {
        cpwait<1>();
        __syncthreads();

        const int s = kt & 1;
        const unsigned ka = sK + s * AT * 4;
        const unsigned va = sV + s * AT * 4;

        // S = Q @ K^T (16 x 64 per warp)
        float sf[8][4];
#pragma unroll
        for (int nt = 0; nt < 8; nt++)
#pragma unroll
            for (int e = 0; e < 4; e++) sf[nt][e] = 0.f;
#pragma unroll
        for (int ks = 0; ks < 8; ks++) {
#pragma unroll
            for (int g = 0; g < 4; g++) {
                unsigned d0, d1, d2, d3;
                ldsm4(d0, d1, d2, d3, ka + g * 4096 + rowb + colb[ks]);
                unsigned b0[2] = { d0, d2 };
                unsigned b1[2] = { d1, d3 };
                mma_tf32(sf[2*g    ], qf[ks], b0);
                mma_tf32(sf[2*g + 1], qf[ks], b1);
            }
        }

        const bool diag = (kt == qt);
#pragma unroll
        for (int nt = 0; nt < 8; nt++) {
            sf[nt][0] *= SC2; sf[nt][1] *= SC2; sf[nt][2] *= SC2; sf[nt][3] *= SC2;
            if (diag) {
                const int kc = nt * 8 + 2 * c4;
                if (kc     > rowL0) sf[nt][0] = -1e30f;
                if (kc + 1 > rowL0) sf[nt][1] = -1e30f;
                if (kc     > rowL1) sf[nt][2] = -1e30f;
                if (kc + 1 > rowL1) sf[nt][3] = -1e30f;
            }
        }

        float mx0 = -1e30f, mx1 = -1e30f;
#pragma unroll
        for (int nt = 0; nt < 8; nt++) {
            mx0 = fmaxf(mx0, fmaxf(sf[nt][0], sf[nt][1]));
            mx1 = fmaxf(mx1, fmaxf(sf[nt][2], sf[nt][3]));
        }
        mx0 = fmaxf(mx0, __shfl_xor_sync(0xffffffffu, mx0, 1));
        mx0 = fmaxf(mx0, __shfl_xor_sync(0xffffffffu, mx0, 2));
        mx1 = fmaxf(mx1, __shfl_xor_sync(0xffffffffu, mx1, 1));
        mx1 = fmaxf(mx1, __shfl_xor_sync(0xffffffffu, mx1, 2));

        const float nm0 = fmaxf(rm0, mx0), nm1 = fmaxf(rm1, mx1);
        const float corr0 = exp2p(rm0 - nm0), corr1 = exp2p(rm1 - nm1);
        rm0 = nm0; rm1 = nm1;

        float s0 = 0.f, s1 = 0.f;
#pragma unroll
        for (int nt = 0; nt < 8; nt++) {
            const float p0 = exp2p(sf[nt][0] - nm0);
            const float p1 = exp2p(sf[nt][1] - nm0);
            const float p2 = exp2p(sf[nt][2] - nm1);
            const float p3 = exp2p(sf[nt][3] - nm1);
            s0 += p0 + p1;  s1 += p2 + p3;
            const int col = nt * 8 + 2 * c4;
            const int u   = col >> 2;
            const int wd  = col & 3;
            Pw[(r4    ) * 64 + ((u ^ r4) << 2) + wd    ] = f2tf32f(p0);
            Pw[(r4    ) * 64 + ((u ^ r4) << 2) + wd + 1] = f2tf32f(p1);
            Pw[(r4 + 8) * 64 + ((u ^ r4) << 2) + wd    ] = f2tf32f(p2);
            Pw[(r4 + 8) * 64 + ((u ^ r4) << 2) + wd + 1] = f2tf32f(p3);
        }
        s0 += __shfl_xor_sync(0xffffffffu, s0, 1);
        s0 += __shfl_xor_sync(0xffffffffu, s0, 2);
        s1 += __shfl_xor_sync(0xffffffffu, s1, 1);
        s1 += __shfl_xor_sync(0xffffffffu, s1, 2);
        rl0 = rl0 * corr0 + s0;
        rl1 = rl1 * corr1 + s1;

#pragma unroll
        for (int dt = 0; dt < 8; dt++) {
            oacc[dt][0] *= corr0; oacc[dt][1] *= corr0;
            oacc[dt][2] *= corr1; oacc[dt][3] *= corr1;
        }
        __syncwarp();

        // O += P @ V^T
#pragma unroll
        for (int ks = 0; ks < 8; ks++) {
            unsigned pf[4];
            ldsm4(pf[0], pf[1], pf[2], pf[3], sP + rowb + colb[ks]);
#pragma unroll
            for (int g = 0; g < 4; g++) {
                unsigned d0, d1, d2, d3;
                ldsm4(d0, d1, d2, d3, va + g * 4096 + rowb + colb[ks]);
                unsigned b0[2] = { d0, d2 };
                unsigned b1[2] = { d1, d3 };
                mma_tf32(oacc[2*g    ], pf, b0);
                mma_tf32(oacc[2*g + 1], pf, b1);
            }
        }

        // all warps done reading stage s before refilling it next iteration
        __syncthreads();
        if (kt + 2 <= qt) {
            const unsigned ka2 = sK + s * AT * 4;   // stage (kt+2)&1 == s
            const unsigned va2 = sV + s * AT * 4;
#pragma unroll
            for (int i = 0; i < 8; i++) {
                const int r = fr + i * 8;
                const unsigned off = (unsigned)((r * 16 + (fu ^ (r & 7))) * 16);
                cpa16(ka2 + off, Kg + (size_t)((kt + 2) * 64 + r) * HD + fu * 4);
                cpa16(va2 + off, Vg + (size_t)r * TSEQ + (kt + 2) * 64 + fu * 4);
            }
        }
        cpcommit();
    }

    const float inv0 = 1.f / rl0;
    const float inv1 = 1.f / rl1;
    const int bb = bh >> 4;
    const int h  = bh & 15;
    const size_t rg = (size_t)(bb * TSEQ + qt * 64 + w * 16 + r4);
    float* O0 = g_attn + rg * D_MODEL + h * HD;
    float* O1 = O0 + 8 * D_MODEL;
#pragma unroll
    for (int dt = 0; dt < 8; dt++) {
        const int dim = dt * 8 + 2 * c4;
        *(float2*)(O0 + dim) = make_float2(f2tf32f(oacc[dt][0] * inv0),
                                           f2tf32f(oacc[dt][1] * inv0));
        *(float2*)(O1 + dim) = make_float2(f2tf32f(oacc[dt][2] * inv1),
                                           f2tf32f(oacc[dt][3] * inv1));
    }
}

// ---------------------------------------------------------------------------
extern "C" void kernel_launch(void* const* d_in, const int* in_sizes, int n_in,
                              void* d_out, int out_size)
{
    const float* x  = (const float*)d_in[0];
    const float* Wq = (const float*)d_in[1];
    const float* Wk = (const float*)d_in[2];
    const float* Wv = (const float*)d_in[3];
    const float* Wo = (const float*)d_in[4];
    float* out = (float*)d_out;

    const int gemm_smem = GEMM_SMEM_BYTES;               // 65536
    const int attn_smem = ATTN_SMEM_BYTES;               // 81920
    cudaFuncSetAttribute(gemm_qkv_tc, cudaFuncAttributeMaxDynamicSharedMemorySize, gemm_smem);
    cudaFuncSetAttribute(gemm_o_tc,   cudaFuncAttributeMaxDynamicSharedMemorySize, gemm_smem);
    cudaFuncSetAttribute(attn_tc,     cudaFuncAttributeMaxDynamicSharedMemorySize, attn_smem);

    cvt_in<<<8192, 256>>>((const float4*)x, (const float4*)Wq, (const float4*)Wk,
                          (const float4*)Wv, (const float4*)Wo);

    dim3 gqkv(1024 / 128, MROWS / 128, 3);
    gemm_qkv_tc<<<gqkv, 128, gemm_smem>>>();

    dim3 gattn(TSEQ / 64, BATCH * NHEADS);
    attn_tc<<<gattn, 128, attn_smem>>>();

    dim3 go(1024 / 128, MROWS / 128);
    gemm_o_tc<<<go, 128, gemm_smem>>>(out);
}

// round 15
// speedup vs baseline: 1.9660x; 1.7054x over previous
#include <cuda_runtime.h>
#include <cuda_fp16.h>
#include <cstddef>
#include <cstdint>

#define D_MODEL 1024
#define NHEADS  16
#define HD      64
#define BATCH   2
#define TSEQ    2048
#define MROWS   (BATCH*TSEQ)   /* 4096 */

// Scratch (device globals): fp16 operands, fp32 only for final output.
__device__ __half g_xh[(size_t)MROWS * D_MODEL];
__device__ __half g_wqh[(size_t)D_MODEL * D_MODEL];
__device__ __half g_wkh[(size_t)D_MODEL * D_MODEL];
__device__ __half g_wvh[(size_t)D_MODEL * D_MODEL];
__device__ __half g_woh[(size_t)D_MODEL * D_MODEL];
__device__ __half g_qh[(size_t)MROWS * D_MODEL];    // [B,H,T,64]
__device__ __half g_kh[(size_t)MROWS * D_MODEL];    // [B,H,T,64]
__device__ __half g_vh[(size_t)MROWS * D_MODEL];    // TRANSPOSED [B,H,64,T]
__device__ __half g_ah[(size_t)MROWS * D_MODEL];    // [B,T,1024]

// ---------------------------------------------------------------------------
// helpers
// ---------------------------------------------------------------------------
__device__ __forceinline__ void mma_f16(float c[4], const unsigned a[4], const unsigned b[2]) {
    asm volatile(
        "mma.sync.aligned.m16n8k16.row.col.f32.f16.f16.f32 "
        "{%0,%1,%2,%3}, {%4,%5,%6,%7}, {%8,%9}, {%0,%1,%2,%3};"
        : "+f"(c[0]), "+f"(c[1]), "+f"(c[2]), "+f"(c[3])
        : "r"(a[0]), "r"(a[1]), "r"(a[2]), "r"(a[3]), "r"(b[0]), "r"(b[1]));
}
__device__ __forceinline__ void ldsm4(unsigned &d0, unsigned &d1, unsigned &d2, unsigned &d3,
                                      unsigned addr) {
    asm volatile("ldmatrix.sync.aligned.m8n8.x4.shared.b16 {%0,%1,%2,%3}, [%4];"
                 : "=r"(d0), "=r"(d1), "=r"(d2), "=r"(d3) : "r"(addr));
}
__device__ __forceinline__ void cpa16(unsigned dst, const void* src) {
    asm volatile("cp.async.cg.shared.global [%0], [%1], 16;" :: "r"(dst), "l"(src));
}
__device__ __forceinline__ void cpcommit() { asm volatile("cp.async.commit_group;"); }
template<int N> __device__ __forceinline__ void cpwait() {
    asm volatile("cp.async.wait_group %0;" :: "n"(N) : "memory");
}

// fast exp2 for x <= 0 (FMA pipe, no MUFU)
__device__ __forceinline__ float exp2p(float x) {
    x = fmaxf(x, -126.f);
    float z = x + 12582912.0f;
    int   n = __float_as_int(z) - 0x4B400000;
    float f = x - (z - 12582912.0f);
    float p = 0.0096181291f;
    p = fmaf(p, f, 0.0555041087f);
    p = fmaf(p, f, 0.2402265069f);
    p = fmaf(p, f, 0.6931471806f);
    p = fmaf(p, f, 1.0f);
    return __int_as_float(__float_as_int(p) + (n << 23));
}

__device__ __forceinline__ unsigned pack_h2(float lo, float hi) {
    __half2 h = __floats2half2_rn(lo, hi);
    return *(unsigned*)&h;
}

// ---------------------------------------------------------------------------
// input pre-conversion: fp32 -> fp16 for x and the 4 weight matrices
// ---------------------------------------------------------------------------
__global__ __launch_bounds__(256) void cvt_in(
    const float4* __restrict__ x,
    const float4* __restrict__ wq, const float4* __restrict__ wk,
    const float4* __restrict__ wv, const float4* __restrict__ wo)
{
    const size_t i = (size_t)blockIdx.x * 256 + threadIdx.x;   // 0 .. 2M-1 float4s
    const float4* src; __half* dst;
    if (i < (1u << 20)) {
        src = x + i;  dst = g_xh + i * 4;
    } else {
        size_t j = i - (1u << 20);
        int ww = (int)(j >> 18);
        size_t o = j & ((1u << 18) - 1);
        const float4* s = (ww == 0) ? wq : (ww == 1) ? wk : (ww == 2) ? wv : wo;
        __half*       d = (ww == 0) ? g_wqh : (ww == 1) ? g_wkh
                                    : (ww == 2) ? g_wvh : g_woh;
        src = s + o; dst = d + o * 4;
    }
    float4 v = *src;
    uint2 o2;
    o2.x = pack_h2(v.x, v.y);
    o2.y = pack_h2(v.z, v.w);
    *(uint2*)dst = o2;
}

// ---------------------------------------------------------------------------
// fp16 GEMM: C = A @ W^T. Block tile 128x128, k-chunk 64 halves (128B rows),
// 4 warps with 64x64 warp tiles, 3-stage cp.async, XOR-swizzled smem,
// ldmatrix.x4 + m16n8k16. 16 k-chunks.
// EPI: 0 plain fp32 out; 1 Q/K permute ([B,H,T,64] fp16); 2 V transpose
// ([B,H,64,T] fp16).
// ---------------------------------------------------------------------------
#define GSTG 32768                       /* A 16KB + B 16KB per stage */
#define GEMM_SMEM_BYTES (3*GSTG)         /* 98304 */

template <int EPI>
__device__ __forceinline__ void gemm_body(const __half* __restrict__ A,
                                          const __half* __restrict__ W,
                                          float* __restrict__ Cf,
                                          __half* __restrict__ Ch)
{
    extern __shared__ __align__(1024) unsigned char gsm[];
    const unsigned sBase = (unsigned)__cvta_generic_to_shared(gsm);

    const int tid  = threadIdx.x;
    const int lane = tid & 31;
    const int warp = tid >> 5;           // 0..3
    const int wm   = warp >> 1;          // 0..1  (64 rows)
    const int wn   = warp & 1;           // 0..1  (64 cols)
    const int bx   = blockIdx.x;
    const int by   = blockIdx.y;

    const int lr16 = lane & 15;
    const int lhi  = lane >> 4;
    const int lx7  = lane & 7;
    const int r4   = lane >> 2;
    const int c4   = lane & 3;

    const int fu = tid & 7;              // 16B unit (8 halves) in 128B row
    const int fr = tid >> 3;             // 0..15
    const __half* Ag = A + (size_t)(by * 128) * 1024 + fu * 8;
    const __half* Wg = W + (size_t)(bx * 128) * 1024 + fu * 8;

    const unsigned a_row = (unsigned)(wm * 64 + lr16) * 128;
    const unsigned b_row = (unsigned)(wn * 64 + lr16) * 128;
    unsigned colb[4];
#pragma unroll
    for (int ks = 0; ks < 4; ks++) colb[ks] = (unsigned)(((ks * 2 + lhi) ^ lx7) * 16);

    float acc[4][8][4];
#pragma unroll
    for (int mt = 0; mt < 4; mt++)
#pragma unroll
        for (int nt = 0; nt < 8; nt++)
#pragma unroll
            for (int e = 0; e < 4; e++) acc[mt][nt][e] = 0.f;

    // prologue: fill stages 0,1 with k-chunks 0,1
#pragma unroll
    for (int pk = 0; pk < 2; pk++) {
        const unsigned ab = sBase + pk * GSTG;
        const unsigned bb = ab + 16384;
#pragma unroll
        for (int i = 0; i < 8; i++) {
            const int r = fr + i * 16;
            const unsigned off = (unsigned)((r * 8 + (fu ^ (r & 7))) * 16);
            cpa16(ab + off, Ag + (size_t)r * 1024 + pk * 64);
            cpa16(bb + off, Wg + (size_t)r * 1024 + pk * 64);
        }
        cpcommit();
    }

    for (int ki = 0; ki < 16; ki++) {
        cpwait<1>();
        __syncthreads();

        if (ki + 2 < 16) {
            const int st = (ki + 2) % 3;
            const unsigned ab = sBase + st * GSTG;
            const unsigned bb = ab + 16384;
#pragma unroll
            for (int i = 0; i < 8; i++) {
                const int r = fr + i * 16;
                const unsigned off = (unsigned)((r * 8 + (fu ^ (r & 7))) * 16);
                cpa16(ab + off, Ag + (size_t)r * 1024 + (ki + 2) * 64);
                cpa16(bb + off, Wg + (size_t)r * 1024 + (ki + 2) * 64);
            }
        }
        cpcommit();

        const int s = ki % 3;
        const unsigned ab = sBase + s * GSTG;
        const unsigned bb = ab + 16384;
#pragma unroll
        for (int ks = 0; ks < 4; ks++) {
            unsigned af[4][4];
#pragma unroll
            for (int mt = 0; mt < 4; mt++)
                ldsm4(af[mt][0], af[mt][1], af[mt][2], af[mt][3],
                      ab + a_row + mt * 2048 + colb[ks]);
            unsigned bf[4][4];
#pragma unroll
            for (int n2 = 0; n2 < 4; n2++)
                ldsm4(bf[n2][0], bf[n2][1], bf[n2][2], bf[n2][3],
                      bb + b_row + n2 * 2048 + colb[ks]);
#pragma unroll
            for (int mt = 0; mt < 4; mt++)
#pragma unroll
                for (int nt = 0; nt < 8; nt++) {
                    const int n2 = nt >> 1, sub = nt & 1;
                    unsigned bq[2] = { bf[n2][sub], bf[n2][sub + 2] };
                    mma_f16(acc[mt][nt], af[mt], bq);
                }
        }
    }

#pragma unroll
    for (int mt = 0; mt < 4; mt++) {
        const int row0 = by * 128 + wm * 64 + mt * 16 + r4;
#pragma unroll
        for (int nt = 0; nt < 8; nt++) {
            const int col = bx * 128 + wn * 64 + nt * 8 + 2 * c4;
            if (EPI == 0) {
                *(float2*)&Cf[(size_t)row0 * 1024 + col] =
                    make_float2(acc[mt][nt][0], acc[mt][nt][1]);
                *(float2*)&Cf[(size_t)(row0 + 8) * 1024 + col] =
                    make_float2(acc[mt][nt][2], acc[mt][nt][3]);
            } else if (EPI == 1) {
                const int h = col >> 6, d = col & 63;
                const int b2 = row0 >> 11, t0 = row0 & 2047;
                __half* base = Ch + (((size_t)(b2 * NHEADS + h)) * TSEQ) * HD + d;
                *(unsigned*)(base + (size_t)t0 * HD) =
                    pack_h2(acc[mt][nt][0], acc[mt][nt][1]);
                *(unsigned*)(base + (size_t)(t0 + 8) * HD) =
                    pack_h2(acc[mt][nt][2], acc[mt][nt][3]);
            } else {
                const int h = col >> 6, d = col & 63;
                const int b2 = row0 >> 11, t0 = row0 & 2047;
                __half* base = Ch + ((size_t)(b2 * NHEADS + h) * HD + d) * TSEQ;
                base[t0]            = __float2half_rn(acc[mt][nt][0]);
                base[TSEQ + t0]     = __float2half_rn(acc[mt][nt][1]);
                base[t0 + 8]        = __float2half_rn(acc[mt][nt][2]);
                base[TSEQ + t0 + 8] = __float2half_rn(acc[mt][nt][3]);
            }
        }
    }
}

__global__ __launch_bounds__(128, 2) void gemm_qkv_tc() {
    if (blockIdx.z == 0)      gemm_body<1>(g_xh, g_wqh, nullptr, g_qh);
    else if (blockIdx.z == 1) gemm_body<1>(g_xh, g_wkh, nullptr, g_kh);
    else                      gemm_body<2>(g_xh, g_wvh, nullptr, g_vh);
}
__global__ __launch_bounds__(128, 2) void gemm_o_tc(float* __restrict__ out) {
    gemm_body<0>(g_ah, g_woh, out, nullptr);
}

// ---------------------------------------------------------------------------
// Flash attention, fp16 operands, fp32 softmax/accum, causal.
// 128 threads (4 warps), 64 q rows per block, 64-key tiles, 2-stage cp.async.
// K tile [key][64d] fp16 (8KB), Vt tile [dim][64t] fp16 (8KB), P per warp
// [16][64] fp16 (2KB). Total smem 40KB -> 3 CTAs/SM.
// ---------------------------------------------------------------------------
#define AKT 8192                          /* bytes per 64x64 fp16 tile */
#define ATTN_SMEM_BYTES (4*AKT + 4*2048)  /* 40960 */

__global__ __launch_bounds__(128, 3) void attn_tc() {
    extern __shared__ __align__(1024) unsigned char asmem[];
    const unsigned sBase = (unsigned)__cvta_generic_to_shared(asmem);
    const unsigned sK = sBase;
    const unsigned sV = sBase + 2 * AKT;

    const int tid  = threadIdx.x;
    const int lane = tid & 31;
    const int w    = tid >> 5;
    const int r4   = lane >> 2;
    const int c4   = lane & 3;
    const int lr16 = lane & 15;
    const int lhi  = lane >> 4;
    const int lx7  = lane & 7;
    const int bh   = blockIdx.y;
    const int qt   = (int)gridDim.x - 1 - (int)blockIdx.x;   // heavy first

    const __half* Kg = g_kh + (size_t)bh * TSEQ * HD;   // [t][d]
    const __half* Vg = g_vh + (size_t)bh * HD * TSEQ;   // [d][t]

    __half* Pw = (__half*)(asmem + 4 * AKT + w * 2048);
    const unsigned sP = sBase + 4 * AKT + w * 2048;

    const int fu = tid & 7;               // 16B unit (8 halves)
    const int fr = tid >> 3;              // 0..15

    // Q fragments: 16 rows x 64 halves, 4 k16 steps
    unsigned qf[4][4];
    {
        const __half* Qb = g_qh + ((size_t)bh * TSEQ + qt * 64 + w * 16) * HD;
#pragma unroll
        for (int ks = 0; ks < 4; ks++) {
            qf[ks][0] = *(const unsigned*)&Qb[(r4    ) * HD + ks*16 + 2*c4    ];
            qf[ks][1] = *(const unsigned*)&Qb[(r4 + 8) * HD + ks*16 + 2*c4    ];
            qf[ks][2] = *(const unsigned*)&Qb[(r4    ) * HD + ks*16 + 8 + 2*c4];
            qf[ks][3] = *(const unsigned*)&Qb[(r4 + 8) * HD + ks*16 + 8 + 2*c4];
        }
    }

    unsigned colb[4];
#pragma unroll
    for (int ks = 0; ks < 4; ks++) colb[ks] = (unsigned)(((ks * 2 + lhi) ^ lx7) * 16);
    const unsigned rowb = (unsigned)lr16 * 128;

    float oacc[8][4];
#pragma unroll
    for (int dt = 0; dt < 8; dt++)
#pragma unroll
        for (int e = 0; e < 4; e++) oacc[dt][e] = 0.f;
    float rm0 = -1e30f, rm1 = -1e30f, rl0 = 0.f, rl1 = 0.f;

    const int rowL0 = w * 16 + r4;
    const int rowL1 = rowL0 + 8;
    const float SC2 = 0.1803368801f;      // (1/8)*log2(e)

    // prologue: fill tiles 0 and 1 into stages 0,1
#pragma unroll
    for (int pk = 0; pk < 2; pk++) {
        if (pk <= qt) {
            const unsigned ka = sK + pk * AKT;
            const unsigned va = sV + pk * AKT;
#pragma unroll
            for (int i = 0; i < 4; i++) {
                const int r = fr + i * 16;
                const unsigned off = (unsigned)((r * 8 + (fu ^ (r & 7))) * 16);
                cpa16(ka + off, Kg + (size_t)(pk * 64 + r) * HD + fu * 8);
                cpa16(va + off, Vg + (size_t)r * TSEQ + pk * 64 + fu * 8);
            }
        }
        cpcommit();
    }

    for (int kt = 0; kt <= qt; kt++) {
        cpwait<1>();
        __syncthreads();

        const int s = kt & 1;
        const unsigned ka = sK + s * AKT;
        const unsigned va = sV + s * AKT;

        // S = Q @ K^T (16 x 64 per warp)
        float sf[8][4];
#pragma unroll
        for (int nt = 0; nt < 8; nt++)
#pragma unroll
            for (int e = 0; e < 4; e++) sf[nt][e] = 0.f;
#pragma unroll
        for (int ks = 0; ks < 4; ks++) {
#pragma unroll
            for (int g = 0; g < 4; g++) {
                unsigned d0, d1, d2, d3;
                ldsm4(d0, d1, d2, d3, ka + g * 2048 + rowb + colb[ks]);
                unsigned b0[2] = { d0, d2 };
                unsigned b1[2] = { d1, d3 };
                mma_f16(sf[2*g    ], qf[ks], b0);
                mma_f16(sf[2*g + 1], qf[ks], b1);
            }
        }

        const bool diag = (kt == qt);
#pragma unroll
        for (int nt = 0; nt < 8; nt++) {
            sf[nt][0] *= SC2; sf[nt][1] *= SC2; sf[nt][2] *= SC2; sf[nt][3] *= SC2;
            if (diag) {
                const int kc = nt * 8 + 2 * c4;
                if (kc     > rowL0) sf[nt][0] = -1e30f;
                if (kc + 1 > rowL0) sf[nt][1] = -1e30f;
                if (kc     > rowL1) sf[nt][2] = -1e30f;
                if (kc + 1 > rowL1) sf[nt][3] = -1e30f;
            }
        }

        float mx0 = -1e30f, mx1 = -1e30f;
#pragma unroll
        for (int nt = 0; nt < 8; nt++) {
            mx0 = fmaxf(mx0, fmaxf(sf[nt][0], sf[nt][1]));
            mx1 = fmaxf(mx1, fmaxf(sf[nt][2], sf[nt][3]));
        }
        mx0 = fmaxf(mx0, __shfl_xor_sync(0xffffffffu, mx0, 1));
        mx0 = fmaxf(mx0, __shfl_xor_sync(0xffffffffu, mx0, 2));
        mx1 = fmaxf(mx1, __shfl_xor_sync(0xffffffffu, mx1, 1));
        mx1 = fmaxf(mx1, __shfl_xor_sync(0xffffffffu, mx1, 2));

        const float nm0 = fmaxf(rm0, mx0), nm1 = fmaxf(rm1, mx1);
        const float corr0 = exp2p(rm0 - nm0), corr1 = exp2p(rm1 - nm1);
        rm0 = nm0; rm1 = nm1;

        float s0 = 0.f, s1 = 0.f;
#pragma unroll
        for (int nt = 0; nt < 8; nt++) {
            const float p0 = exp2p(sf[nt][0] - nm0);
            const float p1 = exp2p(sf[nt][1] - nm0);
            const float p2 = exp2p(sf[nt][2] - nm1);
            const float p3 = exp2p(sf[nt][3] - nm1);
            s0 += p0 + p1;  s1 += p2 + p3;
            // P store: row r, col = nt*8 + 2c4; unit nt swizzled by row&7
            const unsigned lo0 = (unsigned)(r4 * 64 + ((nt ^ (r4 & 7)) << 3) + 2 * c4);
            Pw[lo0] = __float2half_rn(p0);           // stored as pair below
            *(unsigned*)&Pw[lo0] = pack_h2(p0, p1);
            const unsigned lo1 = (unsigned)((r4 + 8) * 64 + ((nt ^ (r4 & 7)) << 3) + 2 * c4);
            *(unsigned*)&Pw[lo1] = pack_h2(p2, p3);
        }
        s0 += __shfl_xor_sync(0xffffffffu, s0, 1);
        s0 += __shfl_xor_sync(0xffffffffu, s0, 2);
        s1 += __shfl_xor_sync(0xffffffffu, s1, 1);
        s1 += __shfl_xor_sync(0xffffffffu, s1, 2);
        rl0 = rl0 * corr0 + s0;
        rl1 = rl1 * corr1 + s1;

#pragma unroll
        for (int dt = 0; dt < 8; dt++) {
            oacc[dt][0] *= corr0; oacc[dt][1] *= corr0;
            oacc[dt][2] *= corr1; oacc[dt][3] *= corr1;
        }
        __syncwarp();

        // O += P @ V^T
#pragma unroll
        for (int ks = 0; ks < 4; ks++) {
            unsigned pf[4];
            ldsm4(pf[0], pf[1], pf[2], pf[3], sP + rowb + colb[ks]);
#pragma unroll
            for (int g = 0; g < 4; g++) {
                unsigned d0, d1, d2, d3;
                ldsm4(d0, d1, d2, d3, va + g * 2048 + rowb + colb[ks]);
                unsigned b0[2] = { d0, d2 };
                unsigned b1[2] = { d1, d3 };
                mma_f16(oacc[2*g    ], pf, b0);
                mma_f16(oacc[2*g + 1], pf, b1);
            }
        }

        // all warps done reading stage s before refilling it next iteration
        __syncthreads();
        if (kt + 2 <= qt) {
            const unsigned ka2 = sK + s * AKT;   // stage (kt+2)&1 == s
            const unsigned va2 = sV + s * AKT;
#pragma unroll
            for (int i = 0; i < 4; i++) {
                const int r = fr + i * 16;
                const unsigned off = (unsigned)((r * 8 + (fu ^ (r & 7))) * 16);
                cpa16(ka2 + off, Kg + (size_t)((kt + 2) * 64 + r) * HD + fu * 8);
                cpa16(va2 + off, Vg + (size_t)r * TSEQ + (kt + 2) * 64 + fu * 8);
            }
        }
        cpcommit();
    }

    const float inv0 = 1.f / rl0;
    const float inv1 = 1.f / rl1;
    const int bb = bh >> 4;
    const int h  = bh & 15;
    const size_t rg = (size_t)(bb * TSEQ + qt * 64 + w * 16 + r4);
    __half* O0 = g_ah + rg * D_MODEL + h * HD;
    __half* O1 = O0 + 8 * D_MODEL;
#pragma unroll
    for (int dt = 0; dt < 8; dt++) {
        const int dim = dt * 8 + 2 * c4;
        *(unsigned*)(O0 + dim) = pack_h2(oacc[dt][0] * inv0, oacc[dt][1] * inv0);
        *(unsigned*)(O1 + dim) = pack_h2(oacc[dt][2] * inv1, oacc[dt][3] * inv1);
    }
}

// ---------------------------------------------------------------------------
extern "C" void kernel_launch(void* const* d_in, const int* in_sizes, int n_in,
                              void* d_out, int out_size)
{
    const float* x  = (const float*)d_in[0];
    const float* Wq = (const float*)d_in[1];
    const float* Wk = (const float*)d_in[2];
    const float* Wv = (const float*)d_in[3];
    const float* Wo = (const float*)d_in[4];
    float* out = (float*)d_out;

    const int gemm_smem = GEMM_SMEM_BYTES;               // 98304
    const int attn_smem = ATTN_SMEM_BYTES;               // 40960
    cudaFuncSetAttribute(gemm_qkv_tc, cudaFuncAttributeMaxDynamicSharedMemorySize, gemm_smem);
    cudaFuncSetAttribute(gemm_o_tc,   cudaFuncAttributeMaxDynamicSharedMemorySize, gemm_smem);
    cudaFuncSetAttribute(attn_tc,     cudaFuncAttributeMaxDynamicSharedMemorySize, attn_smem);

    cvt_in<<<8192, 256>>>((const float4*)x, (const float4*)Wq, (const float4*)Wk,
                          (const float4*)Wv, (const float4*)Wo);

    dim3 gqkv(1024 / 128, MROWS / 128, 3);
    gemm_qkv_tc<<<gqkv, 128, gemm_smem>>>();

    dim3 gattn(TSEQ / 64, BATCH * NHEADS);
    attn_tc<<<gattn, 128, attn_smem>>>();

    dim3 go(1024 / 128, MROWS / 128);
    gemm_o_tc<<<go, 128, gemm_smem>>>(out);
}